// round 1
// baseline (speedup 1.0000x reference)
#include <cuda_runtime.h>
#include <math.h>

// ---------------- problem constants ----------------
constexpr int Nb = 2;
constexpr int Cc = 256;
constexpr int Ss = 4096;      // 64*64
constexpr int Hh = 4;
constexpr int Dh = 64;
constexpr int NH = Nb * Hh;   // 8
constexpr float EPSV = 1e-5f;
constexpr float SCALE = 1.0f / 64.0f;   // 1/sqrt(4096)

// ---------------- device scratch ----------------
__device__ float g_r   [Nb * Ss * Cc];            // residual r [n,s,c]
__device__ float g_norm[Nb * Ss * Cc];            // ln1 output
__device__ float g_Q   [NH * Ss * Dh];
__device__ float g_K   [NH * Ss * Dh];
__device__ float g_V   [NH * Ss * Dh];
__device__ float g_Y   [134217728];               // Yt [nh][k][q]  (512 MB)
__device__ float g_rm  [NH * Ss];                 // per-(nh,k) row max
__device__ float g_ri  [NH * Ss];                 // per-(nh,k) 1/sum
__device__ float g_attn[Nb * Ss * Cc];            // attn_cat [n,s,c]
__device__ float g_u   [Nb * Ss * Cc];            // ln2 output
__device__ float g_h1  [Nb * Ss * Cc];            // gelu(u@W1+b1)
__device__ float g_o   [Nb * Ss * Cc];            // final [n,s,c] before transpose

// ---------------- transpose in: x[n,c,s] -> r[n,s,c] ----------------
__global__ void k_transpose_in(const float* __restrict__ x) {
    __shared__ float t[32][33];
    int n = blockIdx.z;
    int s0 = blockIdx.x * 32, c0 = blockIdx.y * 32;
    int tx = threadIdx.x, ty = threadIdx.y;   // 32, 8
#pragma unroll
    for (int i = 0; i < 4; i++)
        t[ty + 8 * i][tx] = x[((size_t)(n * Cc + c0 + ty + 8 * i)) * Ss + s0 + tx];
    __syncthreads();
#pragma unroll
    for (int i = 0; i < 4; i++)
        g_r[((size_t)(n * Ss + s0 + ty + 8 * i)) * Cc + c0 + tx] = t[tx][ty + 8 * i];
}

// ---------------- transpose out: g_o[n,s,c] -> out[n,c,s] ----------------
__global__ void k_transpose_out(float* __restrict__ out) {
    __shared__ float t[32][33];
    int n = blockIdx.z;
    int s0 = blockIdx.x * 32, c0 = blockIdx.y * 32;
    int tx = threadIdx.x, ty = threadIdx.y;
#pragma unroll
    for (int i = 0; i < 4; i++)
        t[ty + 8 * i][tx] = g_o[((size_t)(n * Ss + s0 + ty + 8 * i)) * Cc + c0 + tx];
    __syncthreads();
#pragma unroll
    for (int i = 0; i < 4; i++)
        out[((size_t)(n * Cc + c0 + ty + 8 * i)) * Ss + s0 + tx] = t[tx][ty + 8 * i];
}

// ---------------- LayerNorm over rows of 256 ----------------
// MODE 0: g_norm = LN(g_r);  MODE 1: g_u = LN(g_attn + g_r)
template <int MODE>
__global__ void k_ln(const float* __restrict__ w, const float* __restrict__ b) {
    int row = blockIdx.x;
    int t = threadIdx.x;   // 256
    size_t idx = (size_t)row * Cc + t;
    float v = (MODE == 0) ? g_r[idx] : (g_attn[idx] + g_r[idx]);

    float s1 = v, s2 = v * v;
#pragma unroll
    for (int o = 16; o; o >>= 1) {
        s1 += __shfl_xor_sync(0xffffffffu, s1, o);
        s2 += __shfl_xor_sync(0xffffffffu, s2, o);
    }
    __shared__ float sm1[8], sm2[8];
    __shared__ float mb, rb;
    int w8 = t >> 5, lane = t & 31;
    if (!lane) { sm1[w8] = s1; sm2[w8] = s2; }
    __syncthreads();
    if (t == 0) {
        float a = 0.f, q = 0.f;
#pragma unroll
        for (int i = 0; i < 8; i++) { a += sm1[i]; q += sm2[i]; }
        float mean = a * (1.0f / Cc);
        float var = q * (1.0f / Cc) - mean * mean;
        mb = mean;
        rb = rsqrtf(var + EPSV);
    }
    __syncthreads();
    float o = (v - mb) * rb * w[t] + b[t];
    if (MODE == 0) g_norm[idx] = o; else g_u[idx] = o;
}

// ---------------- QKV projection GEMM ----------------
// per (n,h): Out[4096x64] = norm_n[4096x256] @ W_h[256x64]
// grid (Ss/128, NH), block 128, TM=TN=8
template <int WHICH>
__global__ __launch_bounds__(128) void k_qkv(const float* __restrict__ Wb) {
    int nh = blockIdx.y;
    int n = nh >> 2, h = nh & 3;
    int m0 = blockIdx.x * 128;
    const float* A = g_norm + (size_t)n * Ss * Cc;
    const float* W = Wb + (size_t)h * Cc * Dh;
    float* Out = (WHICH == 0 ? g_Q : WHICH == 1 ? g_K : g_V) + (size_t)nh * Ss * Dh;

    __shared__ float As[16][128];
    __shared__ float Bs[16][64];
    float acc[8][8] = {};
    int tid = threadIdx.x;
    int tq = tid >> 3, td = tid & 7;

    for (int kb = 0; kb < Cc; kb += 16) {
#pragma unroll
        for (int i = 0; i < 4; i++) {
            int idx = tid + i * 128;
            int r = idx >> 2, c4 = idx & 3;
            float4 v = *(const float4*)(A + (size_t)(m0 + r) * Cc + kb + c4 * 4);
            As[c4 * 4 + 0][r] = v.x; As[c4 * 4 + 1][r] = v.y;
            As[c4 * 4 + 2][r] = v.z; As[c4 * 4 + 3][r] = v.w;
        }
#pragma unroll
        for (int i = 0; i < 2; i++) {
            int idx = tid + i * 128;
            int r = idx >> 4, c4 = idx & 15;
            *(float4*)&Bs[r][c4 * 4] = *(const float4*)(W + (size_t)(kb + r) * Dh + c4 * 4);
        }
        __syncthreads();
#pragma unroll
        for (int kk = 0; kk < 16; kk++) {
            float a[8], bb[8];
            *(float4*)a       = *(const float4*)&As[kk][tq * 8];
            *(float4*)(a + 4) = *(const float4*)&As[kk][tq * 8 + 4];
            *(float4*)bb       = *(const float4*)&Bs[kk][td * 8];
            *(float4*)(bb + 4) = *(const float4*)&Bs[kk][td * 8 + 4];
#pragma unroll
            for (int i = 0; i < 8; i++)
#pragma unroll
                for (int j = 0; j < 8; j++)
                    acc[i][j] = fmaf(a[i], bb[j], acc[i][j]);
        }
        __syncthreads();
    }
#pragma unroll
    for (int i = 0; i < 8; i++) {
        size_t o = (size_t)(m0 + tq * 8 + i) * Dh + td * 8;
        *(float4*)(Out + o)     = make_float4(acc[i][0], acc[i][1], acc[i][2], acc[i][3]);
        *(float4*)(Out + o + 4) = make_float4(acc[i][4], acc[i][5], acc[i][6], acc[i][7]);
    }
}

// ---------------- Yt = (K @ Q^T) * SCALE ----------------
// per (n,h): Yt[k][q] = sum_d K[k,d]*Q[q,d] * SCALE
// grid (Ss/128, Ss/128, NH), block 256, 128x128 tile, TM=TN=8
__global__ __launch_bounds__(256) void k_yt() {
    int nh = blockIdx.z;
    const float* Kp = g_K + (size_t)nh * Ss * Dh;
    const float* Qp = g_Q + (size_t)nh * Ss * Dh;
    float* Yp = g_Y + (size_t)nh * Ss * Ss;
    int k0 = blockIdx.y * 128;   // rows (k)
    int q0 = blockIdx.x * 128;   // cols (q)

    __shared__ float As[16][128];   // [d][k]
    __shared__ float Bs[16][128];   // [d][q]
    float acc[8][8] = {};
    int tid = threadIdx.x;
    int tr = tid >> 4, tc = tid & 15;

    for (int d0 = 0; d0 < Dh; d0 += 16) {
#pragma unroll
        for (int i = 0; i < 2; i++) {
            int idx = tid + i * 256;
            int r = idx >> 2, c4 = idx & 3;
            float4 v = *(const float4*)(Kp + (size_t)(k0 + r) * Dh + d0 + c4 * 4);
            As[c4 * 4 + 0][r] = v.x; As[c4 * 4 + 1][r] = v.y;
            As[c4 * 4 + 2][r] = v.z; As[c4 * 4 + 3][r] = v.w;
            float4 u = *(const float4*)(Qp + (size_t)(q0 + r) * Dh + d0 + c4 * 4);
            Bs[c4 * 4 + 0][r] = u.x; Bs[c4 * 4 + 1][r] = u.y;
            Bs[c4 * 4 + 2][r] = u.z; Bs[c4 * 4 + 3][r] = u.w;
        }
        __syncthreads();
#pragma unroll
        for (int dd = 0; dd < 16; dd++) {
            float a[8], bb[8];
            *(float4*)a       = *(const float4*)&As[dd][tr * 8];
            *(float4*)(a + 4) = *(const float4*)&As[dd][tr * 8 + 4];
            *(float4*)bb       = *(const float4*)&Bs[dd][tc * 8];
            *(float4*)(bb + 4) = *(const float4*)&Bs[dd][tc * 8 + 4];
#pragma unroll
            for (int i = 0; i < 8; i++)
#pragma unroll
                for (int j = 0; j < 8; j++)
                    acc[i][j] = fmaf(a[i], bb[j], acc[i][j]);
        }
        __syncthreads();
    }
#pragma unroll
    for (int i = 0; i < 8; i++) {
        size_t o = (size_t)(k0 + tr * 8 + i) * Ss + q0 + tc * 8;
        *(float4*)(Yp + o) = make_float4(acc[i][0] * SCALE, acc[i][1] * SCALE,
                                         acc[i][2] * SCALE, acc[i][3] * SCALE);
        *(float4*)(Yp + o + 4) = make_float4(acc[i][4] * SCALE, acc[i][5] * SCALE,
                                             acc[i][6] * SCALE, acc[i][7] * SCALE);
    }
}

// ---------------- per-row (k) softmax stats over q ----------------
// grid NH*Ss blocks, 256 threads; 16 elems/thread held in registers
__global__ __launch_bounds__(256) void k_rowstats() {
    int row = blockIdx.x;
    int t = threadIdx.x;
    const float* Yp = g_Y + (size_t)row * Ss;
    float4 v[4];
#pragma unroll
    for (int j = 0; j < 4; j++)
        v[j] = *(const float4*)(Yp + (t + j * 256) * 4);

    float m = -3.0e38f;
#pragma unroll
    for (int j = 0; j < 4; j++)
        m = fmaxf(m, fmaxf(fmaxf(v[j].x, v[j].y), fmaxf(v[j].z, v[j].w)));
#pragma unroll
    for (int o = 16; o; o >>= 1) m = fmaxf(m, __shfl_xor_sync(0xffffffffu, m, o));
    __shared__ float sm[8];
    __shared__ float bM;
    int w8 = t >> 5, lane = t & 31;
    if (!lane) sm[w8] = m;
    __syncthreads();
    if (t == 0) {
        float mm = sm[0];
#pragma unroll
        for (int i = 1; i < 8; i++) mm = fmaxf(mm, sm[i]);
        bM = mm;
    }
    __syncthreads();
    float M = bM;
    float s = 0.f;
#pragma unroll
    for (int j = 0; j < 4; j++)
        s += __expf(v[j].x - M) + __expf(v[j].y - M) +
             __expf(v[j].z - M) + __expf(v[j].w - M);
#pragma unroll
    for (int o = 16; o; o >>= 1) s += __shfl_xor_sync(0xffffffffu, s, o);
    if (!lane) sm[w8] = s;
    __syncthreads();
    if (t == 0) {
        float ss = 0.f;
#pragma unroll
        for (int i = 0; i < 8; i++) ss += sm[i];
        g_rm[row] = M;
        g_ri[row] = 1.0f / ss;
    }
}

// ---------------- attn = Z^T @ V, fused exp-normalize on load ----------------
// per (n,h): out[q,d] = sum_k exp(Yt[k,q]-m_k)*inv_k * V[k,d]
// grid (Ss/128, NH), block 128, BM=128(q), BN=64(d), BK=16(k), TM=TN=8
__global__ __launch_bounds__(128) void k_attn() {
    int nh = blockIdx.y;
    int n = nh >> 2, h = nh & 3;
    int q0 = blockIdx.x * 128;
    const float* Yp = g_Y + (size_t)nh * Ss * Ss;
    const float* Vp = g_V + (size_t)nh * Ss * Dh;
    const float* mrow = g_rm + nh * Ss;
    const float* irow = g_ri + nh * Ss;

    __shared__ float As[16][128];   // [k][q] z-values
    __shared__ float Bs[16][64];    // [k][d]
    float acc[8][8] = {};
    int tid = threadIdx.x;
    int tq = tid >> 3, td = tid & 7;

    for (int kb = 0; kb < Ss; kb += 16) {
#pragma unroll
        for (int i = 0; i < 4; i++) {
            int idx = tid + i * 128;
            int r = idx >> 5, c4 = idx & 31;
            int k = kb + r;
            float mk = mrow[k], ik = irow[k];
            float4 v = *(const float4*)(Yp + (size_t)k * Ss + q0 + c4 * 4);
            float4 z;
            z.x = __expf(v.x - mk) * ik;
            z.y = __expf(v.y - mk) * ik;
            z.z = __expf(v.z - mk) * ik;
            z.w = __expf(v.w - mk) * ik;
            *(float4*)&As[r][c4 * 4] = z;
        }
#pragma unroll
        for (int i = 0; i < 2; i++) {
            int idx = tid + i * 128;
            int r = idx >> 4, c4 = idx & 15;
            *(float4*)&Bs[r][c4 * 4] = *(const float4*)(Vp + (size_t)(kb + r) * Dh + c4 * 4);
        }
        __syncthreads();
#pragma unroll
        for (int kk = 0; kk < 16; kk++) {
            float a[8], bb[8];
            *(float4*)a       = *(const float4*)&As[kk][tq * 8];
            *(float4*)(a + 4) = *(const float4*)&As[kk][tq * 8 + 4];
            *(float4*)bb       = *(const float4*)&Bs[kk][td * 8];
            *(float4*)(bb + 4) = *(const float4*)&Bs[kk][td * 8 + 4];
#pragma unroll
            for (int i = 0; i < 8; i++)
#pragma unroll
                for (int j = 0; j < 8; j++)
                    acc[i][j] = fmaf(a[i], bb[j], acc[i][j]);
        }
        __syncthreads();
    }
    // write attn_cat[n, q, h*64 + d]
#pragma unroll
    for (int i = 0; i < 8; i++) {
        int q = q0 + tq * 8 + i;
        size_t o = ((size_t)n * Ss + q) * Cc + h * Dh + td * 8;
        *(float4*)(g_attn + o)     = make_float4(acc[i][0], acc[i][1], acc[i][2], acc[i][3]);
        *(float4*)(g_attn + o + 4) = make_float4(acc[i][4], acc[i][5], acc[i][6], acc[i][7]);
    }
}

// ---------------- MLP GEMMs ----------------
// MODE 0: g_h1 = gelu(g_u @ W1 + b1)
// MODE 1: g_o  = g_h1 @ W2 + b2 + g_attn
// M=8192, N=256, K=256. grid (64, 4), block 128, BM=128, BN=64, TM=TN=8
template <int MODE>
__global__ __launch_bounds__(128) void k_mlp(const float* __restrict__ W,
                                             const float* __restrict__ bias) {
    int m0 = blockIdx.x * 128;
    int n0 = blockIdx.y * 64;
    const float* A = (MODE == 0) ? g_u : g_h1;

    __shared__ float As[16][128];
    __shared__ float Bs[16][64];
    float acc[8][8] = {};
    int tid = threadIdx.x;
    int tq = tid >> 3, td = tid & 7;

    for (int kb = 0; kb < Cc; kb += 16) {
#pragma unroll
        for (int i = 0; i < 4; i++) {
            int idx = tid + i * 128;
            int r = idx >> 2, c4 = idx & 3;
            float4 v = *(const float4*)(A + (size_t)(m0 + r) * Cc + kb + c4 * 4);
            As[c4 * 4 + 0][r] = v.x; As[c4 * 4 + 1][r] = v.y;
            As[c4 * 4 + 2][r] = v.z; As[c4 * 4 + 3][r] = v.w;
        }
#pragma unroll
        for (int i = 0; i < 2; i++) {
            int idx = tid + i * 128;
            int r = idx >> 4, c4 = idx & 15;
            *(float4*)&Bs[r][c4 * 4] = *(const float4*)(W + (size_t)(kb + r) * Cc + n0 + c4 * 4);
        }
        __syncthreads();
#pragma unroll
        for (int kk = 0; kk < 16; kk++) {
            float a[8], bb[8];
            *(float4*)a       = *(const float4*)&As[kk][tq * 8];
            *(float4*)(a + 4) = *(const float4*)&As[kk][tq * 8 + 4];
            *(float4*)bb       = *(const float4*)&Bs[kk][td * 8];
            *(float4*)(bb + 4) = *(const float4*)&Bs[kk][td * 8 + 4];
#pragma unroll
            for (int i = 0; i < 8; i++)
#pragma unroll
                for (int j = 0; j < 8; j++)
                    acc[i][j] = fmaf(a[i], bb[j], acc[i][j]);
        }
        __syncthreads();
    }
#pragma unroll
    for (int i = 0; i < 8; i++) {
        int row = m0 + tq * 8 + i;
        float vals[8];
#pragma unroll
        for (int j = 0; j < 8; j++) {
            int col = n0 + td * 8 + j;
            float val = acc[i][j] + bias[col];
            if (MODE == 0) {
                val = 0.5f * val * (1.0f + erff(val * 0.70710678118654752f));
            } else {
                val += g_attn[(size_t)row * Cc + col];
            }
            vals[j] = val;
        }
        size_t o = (size_t)row * Cc + n0 + td * 8;
        float* Out = (MODE == 0) ? g_h1 : g_o;
        *(float4*)(Out + o)     = make_float4(vals[0], vals[1], vals[2], vals[3]);
        *(float4*)(Out + o + 4) = make_float4(vals[4], vals[5], vals[6], vals[7]);
    }
}

// ---------------- launch ----------------
extern "C" void kernel_launch(void* const* d_in, const int* in_sizes, int n_in,
                              void* d_out, int out_size) {
    const float* x     = (const float*)d_in[0];
    const float* ln1_w = (const float*)d_in[1];
    const float* ln1_b = (const float*)d_in[2];
    const float* WQ    = (const float*)d_in[3];
    const float* WK    = (const float*)d_in[4];
    const float* WV    = (const float*)d_in[5];
    const float* ln2_w = (const float*)d_in[6];
    const float* ln2_b = (const float*)d_in[7];
    const float* W1    = (const float*)d_in[8];
    const float* b1    = (const float*)d_in[9];
    const float* W2    = (const float*)d_in[10];
    const float* b2    = (const float*)d_in[11];
    float* out = (float*)d_out;

    dim3 tb(32, 8);
    k_transpose_in<<<dim3(Ss / 32, Cc / 32, Nb), tb>>>(x);
    k_ln<0><<<Nb * Ss, 256>>>(ln1_w, ln1_b);

    k_qkv<0><<<dim3(Ss / 128, NH), 128>>>(WQ);
    k_qkv<1><<<dim3(Ss / 128, NH), 128>>>(WK);
    k_qkv<2><<<dim3(Ss / 128, NH), 128>>>(WV);

    k_yt<<<dim3(Ss / 128, Ss / 128, NH), 256>>>();
    k_rowstats<<<NH * Ss, 256>>>();
    k_attn<<<dim3(Ss / 128, NH), 128>>>();

    k_ln<1><<<Nb * Ss, 256>>>(ln2_w, ln2_b);
    k_mlp<0><<<dim3(64, 4), 128>>>(W1, b1);
    k_mlp<1><<<dim3(64, 4), 128>>>(W2, b2);

    k_transpose_out<<<dim3(Ss / 32, Cc / 32, Nb), tb>>>(out);
}

// round 3
// speedup vs baseline: 2.8681x; 2.8681x over previous
#include <cuda_runtime.h>
#include <cuda_fp16.h>
#include <cstdint>
#include <stdint.h>
#include <math.h>

// ---------------- problem constants ----------------
constexpr int Nb = 2;
constexpr int Cc = 256;
constexpr int Ss = 4096;
constexpr int Hh = 4;
constexpr int Dh = 64;
constexpr int NH = Nb * Hh;
constexpr float EPSV = 1e-5f;
constexpr float SCALE = 1.0f / 64.0f;

// ---------------- device scratch ----------------
__device__ float  g_r    [Nb * Ss * Cc];
__device__ __half g_normh[Nb * Ss * Cc];
__device__ __half g_Qh   [NH * Ss * Dh];
__device__ __half g_Kh   [NH * Ss * Dh];
__device__ __half g_Vh   [NH * Ss * Dh];
__device__ __half g_Yh   [(size_t)NH * Ss * Ss];   // 256 MB, Yt [nh][k][q]
__device__ float  g_rm   [NH * Ss];
__device__ float  g_ri   [NH * Ss];
__device__ float  g_attn [Nb * Ss * Cc];
__device__ float  g_u    [Nb * Ss * Cc];
__device__ float  g_h1   [Nb * Ss * Cc];
__device__ float  g_o    [Nb * Ss * Cc];

// ---------------- mma helpers ----------------
__device__ __forceinline__ unsigned smem_u32(const void* p) {
    return (unsigned)__cvta_generic_to_shared(p);
}
__device__ __forceinline__ void ldmx4(unsigned* r, unsigned a) {
    asm volatile("ldmatrix.sync.aligned.m8n8.x4.shared.b16 {%0,%1,%2,%3},[%4];"
                 : "=r"(r[0]), "=r"(r[1]), "=r"(r[2]), "=r"(r[3]) : "r"(a));
}
__device__ __forceinline__ void ldmx4t(unsigned* r, unsigned a) {
    asm volatile("ldmatrix.sync.aligned.m8n8.x4.trans.shared.b16 {%0,%1,%2,%3},[%4];"
                 : "=r"(r[0]), "=r"(r[1]), "=r"(r[2]), "=r"(r[3]) : "r"(a));
}
__device__ __forceinline__ void mma16816(float* c, const unsigned* a, const unsigned* b) {
    asm volatile(
        "mma.sync.aligned.m16n8k16.row.col.f32.f16.f16.f32 "
        "{%0,%1,%2,%3},{%4,%5,%6,%7},{%8,%9},{%0,%1,%2,%3};"
        : "+f"(c[0]), "+f"(c[1]), "+f"(c[2]), "+f"(c[3])
        : "r"(a[0]), "r"(a[1]), "r"(a[2]), "r"(a[3]), "r"(b[0]), "r"(b[1]));
}

// ---------------- transpose in: x[n,c,s] -> r[n,s,c] ----------------
__global__ void k_transpose_in(const float* __restrict__ x) {
    __shared__ float t[32][33];
    int n = blockIdx.z;
    int s0 = blockIdx.x * 32, c0 = blockIdx.y * 32;
    int tx = threadIdx.x, ty = threadIdx.y;
#pragma unroll
    for (int i = 0; i < 4; i++)
        t[ty + 8 * i][tx] = x[((size_t)(n * Cc + c0 + ty + 8 * i)) * Ss + s0 + tx];
    __syncthreads();
#pragma unroll
    for (int i = 0; i < 4; i++)
        g_r[((size_t)(n * Ss + s0 + ty + 8 * i)) * Cc + c0 + tx] = t[tx][ty + 8 * i];
}

// ---------------- transpose out ----------------
__global__ void k_transpose_out(float* __restrict__ out) {
    __shared__ float t[32][33];
    int n = blockIdx.z;
    int s0 = blockIdx.x * 32, c0 = blockIdx.y * 32;
    int tx = threadIdx.x, ty = threadIdx.y;
#pragma unroll
    for (int i = 0; i < 4; i++)
        t[ty + 8 * i][tx] = g_o[((size_t)(n * Ss + s0 + ty + 8 * i)) * Cc + c0 + tx];
    __syncthreads();
#pragma unroll
    for (int i = 0; i < 4; i++)
        out[((size_t)(n * Cc + c0 + ty + 8 * i)) * Ss + s0 + tx] = t[tx][ty + 8 * i];
}

// ---------------- LayerNorm ----------------
// MODE 0: g_normh = half(LN(g_r));  MODE 1: g_u = LN(g_attn + g_r)
template <int MODE>
__global__ void k_ln(const float* __restrict__ w, const float* __restrict__ b) {
    int row = blockIdx.x;
    int t = threadIdx.x;
    size_t idx = (size_t)row * Cc + t;
    float v = (MODE == 0) ? g_r[idx] : (g_attn[idx] + g_r[idx]);

    float s1 = v, s2 = v * v;
#pragma unroll
    for (int o = 16; o; o >>= 1) {
        s1 += __shfl_xor_sync(0xffffffffu, s1, o);
        s2 += __shfl_xor_sync(0xffffffffu, s2, o);
    }
    __shared__ float sm1[8], sm2[8];
    __shared__ float mb, rb;
    int w8 = t >> 5, lane = t & 31;
    if (!lane) { sm1[w8] = s1; sm2[w8] = s2; }
    __syncthreads();
    if (t == 0) {
        float a = 0.f, q = 0.f;
#pragma unroll
        for (int i = 0; i < 8; i++) { a += sm1[i]; q += sm2[i]; }
        float mean = a * (1.0f / Cc);
        float var = q * (1.0f / Cc) - mean * mean;
        mb = mean;
        rb = rsqrtf(var + EPSV);
    }
    __syncthreads();
    float o = (v - mb) * rb * w[t] + b[t];
    if (MODE == 0) g_normh[idx] = __float2half(o);
    else g_u[idx] = o;
}

// ---------------- QKV projection, fp16 mma ----------------
// grid (32, 12, 2): y -> (which, h). Block 256 = 8 warps (4m x 2n).
__global__ __launch_bounds__(256) void k_qkv(const float* __restrict__ WQ,
                                             const float* __restrict__ WK,
                                             const float* __restrict__ WV) {
    int which = blockIdx.y >> 2;
    int h = blockIdx.y & 3;
    int n = blockIdx.z;
    int m0 = blockIdx.x * 128;
    const float* W = (which == 0 ? WQ : which == 1 ? WK : WV) + h * Cc * Dh;
    __half* Out = (which == 0 ? g_Qh : which == 1 ? g_Kh : g_Vh) + (size_t)(n * 4 + h) * Ss * Dh;
    const __half* A = g_normh + (size_t)n * Ss * Cc;

    __shared__ __half As[128][88];
    __shared__ __half Bs[64][88];
    int tid = threadIdx.x, lane = tid & 31, wid = tid >> 5;
    int wm = (wid >> 1) * 32;
    int wn = (wid & 1) * 32;
    float acc[2][4][4] = {};

    for (int kb = 0; kb < Cc; kb += 64) {
#pragma unroll
        for (int i = 0; i < 4; i++) {
            int idx = tid + i * 256;
            int r = idx >> 3, c8 = idx & 7;
            *(float4*)&As[r][c8 * 8] = *(const float4*)(A + (size_t)(m0 + r) * Cc + kb + c8 * 8);
        }
#pragma unroll
        for (int i = 0; i < 4; i++) {
            int idx = tid + i * 256;
            int r = idx >> 4, c4 = idx & 15;
            float4 v = *(const float4*)(W + (size_t)(kb + r) * Dh + c4 * 4);
            __half2* d = (__half2*)&Bs[r][c4 * 4];
            d[0] = __floats2half2_rn(v.x, v.y);
            d[1] = __floats2half2_rn(v.z, v.w);
        }
        __syncthreads();
#pragma unroll
        for (int kk = 0; kk < 64; kk += 16) {
            unsigned a[2][4], b[4][2];
#pragma unroll
            for (int mi = 0; mi < 2; mi++)
                ldmx4(a[mi], smem_u32(&As[wm + mi * 16 + (lane & 15)][kk + (lane >> 4) * 8]));
#pragma unroll
            for (int p = 0; p < 2; p++) {
                unsigned r4[4];
                ldmx4t(r4, smem_u32(&Bs[kk + (lane & 7) + ((lane >> 3) & 1) * 8]
                                       [wn + p * 16 + (lane >> 4) * 8]));
                b[2 * p][0] = r4[0]; b[2 * p][1] = r4[1];
                b[2 * p + 1][0] = r4[2]; b[2 * p + 1][1] = r4[3];
            }
#pragma unroll
            for (int mi = 0; mi < 2; mi++)
#pragma unroll
                for (int nj = 0; nj < 4; nj++)
                    mma16816(acc[mi][nj], a[mi], b[nj]);
        }
        __syncthreads();
    }
#pragma unroll
    for (int mi = 0; mi < 2; mi++) {
        int r = m0 + wm + mi * 16 + (lane >> 2);
#pragma unroll
        for (int nj = 0; nj < 4; nj++) {
            int c = wn + nj * 8 + 2 * (lane & 3);
            *(__half2*)(Out + (size_t)r * Dh + c) =
                __floats2half2_rn(acc[mi][nj][0], acc[mi][nj][1]);
            *(__half2*)(Out + (size_t)(r + 8) * Dh + c) =
                __floats2half2_rn(acc[mi][nj][2], acc[mi][nj][3]);
        }
    }
}

// ---------------- Yt = (K @ Q^T)*SCALE, fp16 mma ----------------
// grid (32 q, 32 k, 8 nh), block 256 = 8 warps (2m x 4n), tile 128k x 128q
__global__ __launch_bounds__(256) void k_yt() {
    int nh = blockIdx.z;
    int k0 = blockIdx.y * 128, q0 = blockIdx.x * 128;
    const __half* Kp = g_Kh + (size_t)nh * Ss * Dh;
    const __half* Qp = g_Qh + (size_t)nh * Ss * Dh;
    __half* Yp = g_Yh + (size_t)nh * Ss * Ss;

    __shared__ __half As[128][88];
    __shared__ __half Bs[128][88];
    int tid = threadIdx.x, lane = tid & 31, wid = tid >> 5;
    int wm = (wid >> 2) * 64;
    int wn = (wid & 3) * 32;
    float acc[4][4][4] = {};

#pragma unroll
    for (int i = 0; i < 4; i++) {
        int idx = tid + i * 256;
        int r = idx >> 3, c8 = idx & 7;
        *(float4*)&As[r][c8 * 8] = *(const float4*)(Kp + (size_t)(k0 + r) * Dh + c8 * 8);
        *(float4*)&Bs[r][c8 * 8] = *(const float4*)(Qp + (size_t)(q0 + r) * Dh + c8 * 8);
    }
    __syncthreads();
#pragma unroll
    for (int kk = 0; kk < 64; kk += 16) {
        unsigned a[4][4], b[4][2];
#pragma unroll
        for (int mi = 0; mi < 4; mi++)
            ldmx4(a[mi], smem_u32(&As[wm + mi * 16 + (lane & 15)][kk + (lane >> 4) * 8]));
#pragma unroll
        for (int p = 0; p < 2; p++) {
            unsigned r4[4];
            ldmx4(r4, smem_u32(&Bs[wn + p * 16 + (lane & 7) + (lane >> 4) * 8]
                                  [kk + ((lane >> 3) & 1) * 8]));
            b[2 * p][0] = r4[0]; b[2 * p][1] = r4[1];
            b[2 * p + 1][0] = r4[2]; b[2 * p + 1][1] = r4[3];
        }
#pragma unroll
        for (int mi = 0; mi < 4; mi++)
#pragma unroll
            for (int nj = 0; nj < 4; nj++)
                mma16816(acc[mi][nj], a[mi], b[nj]);
    }
#pragma unroll
    for (int mi = 0; mi < 4; mi++) {
        int r = k0 + wm + mi * 16 + (lane >> 2);
#pragma unroll
        for (int nj = 0; nj < 4; nj++) {
            int c = q0 + wn + nj * 8 + 2 * (lane & 3);
            *(__half2*)(Yp + (size_t)r * Ss + c) =
                __floats2half2_rn(acc[mi][nj][0] * SCALE, acc[mi][nj][1] * SCALE);
            *(__half2*)(Yp + (size_t)(r + 8) * Ss + c) =
                __floats2half2_rn(acc[mi][nj][2] * SCALE, acc[mi][nj][3] * SCALE);
        }
    }
}

// ---------------- per-k-row softmax stats over q ----------------
__global__ __launch_bounds__(256) void k_rowstats() {
    int row = blockIdx.x;
    int t = threadIdx.x;
    const __half* Yp = g_Yh + (size_t)row * Ss;
    float v[16];
#pragma unroll
    for (int j = 0; j < 2; j++) {
        float4 f = *(const float4*)(Yp + (t + j * 256) * 8);
        const __half2* h = (const __half2*)&f;
#pragma unroll
        for (int u = 0; u < 4; u++) {
            float2 p = __half22float2(h[u]);
            v[j * 8 + 2 * u] = p.x; v[j * 8 + 2 * u + 1] = p.y;
        }
    }
    float m = -3.0e38f;
#pragma unroll
    for (int j = 0; j < 16; j++) m = fmaxf(m, v[j]);
#pragma unroll
    for (int o = 16; o; o >>= 1) m = fmaxf(m, __shfl_xor_sync(0xffffffffu, m, o));
    __shared__ float sm[8];
    __shared__ float bM;
    int w8 = t >> 5, lane = t & 31;
    if (!lane) sm[w8] = m;
    __syncthreads();
    if (t == 0) {
        float mm = sm[0];
#pragma unroll
        for (int i = 1; i < 8; i++) mm = fmaxf(mm, sm[i]);
        bM = mm;
    }
    __syncthreads();
    float M = bM, s = 0.f;
#pragma unroll
    for (int j = 0; j < 16; j++) s += __expf(v[j] - M);
#pragma unroll
    for (int o = 16; o; o >>= 1) s += __shfl_xor_sync(0xffffffffu, s, o);
    if (!lane) sm[w8] = s;
    __syncthreads();
    if (t == 0) {
        float ss = 0.f;
#pragma unroll
        for (int i = 0; i < 8; i++) ss += sm[i];
        g_rm[row] = M;
        g_ri[row] = 1.0f / ss;
    }
}

// ---------------- attn = Z^T @ V, exp fused, fp16 mma ----------------
// grid (32 qtiles, 8 nh), block 256 = 8 warps (4m x 2n); out tile 128q x 64d
__global__ __launch_bounds__(256) void k_attn() {
    int nh = blockIdx.y, n = nh >> 2, h = nh & 3;
    int q0 = blockIdx.x * 128;
    const __half* Yp = g_Yh + (size_t)nh * Ss * Ss;
    const __half* Vp = g_Vh + (size_t)nh * Ss * Dh;
    const float* mrow = g_rm + nh * Ss;
    const float* irow = g_ri + nh * Ss;

    __shared__ __half Zs[64][136];
    __shared__ __half Vs[64][88];
    int tid = threadIdx.x, lane = tid & 31, wid = tid >> 5;
    int wm = (wid >> 1) * 32;
    int wn = (wid & 1) * 32;
    float acc[2][4][4] = {};

    for (int kb = 0; kb < Ss; kb += 64) {
#pragma unroll
        for (int i = 0; i < 4; i++) {
            int idx = tid + i * 256;
            int r = idx >> 4, c = idx & 15;
            int k = kb + r;
            float mk = mrow[k], ik = irow[k];
            float4 f = *(const float4*)(Yp + (size_t)k * Ss + q0 + c * 8);
            const __half2* hh = (const __half2*)&f;
            __half2 z[4];
#pragma unroll
            for (int u = 0; u < 4; u++) {
                float2 p = __half22float2(hh[u]);
                z[u] = __floats2half2_rn(__expf(p.x - mk) * ik, __expf(p.y - mk) * ik);
            }
            *(float4*)&Zs[r][c * 8] = *(float4*)z;
        }
#pragma unroll
        for (int i = 0; i < 2; i++) {
            int idx = tid + i * 256;
            int r = idx >> 3, c8 = idx & 7;
            *(float4*)&Vs[r][c8 * 8] = *(const float4*)(Vp + (size_t)(kb + r) * Dh + c8 * 8);
        }
        __syncthreads();
#pragma unroll
        for (int kk = 0; kk < 64; kk += 16) {
            unsigned a[2][4], b[4][2];
#pragma unroll
            for (int mi = 0; mi < 2; mi++)
                ldmx4t(a[mi], smem_u32(&Zs[kk + (lane & 7) + (lane >> 4) * 8]
                                          [wm + mi * 16 + ((lane >> 3) & 1) * 8]));
#pragma unroll
            for (int p = 0; p < 2; p++) {
                unsigned r4[4];
                ldmx4t(r4, smem_u32(&Vs[kk + (lane & 7) + ((lane >> 3) & 1) * 8]
                                       [wn + p * 16 + (lane >> 4) * 8]));
                b[2 * p][0] = r4[0]; b[2 * p][1] = r4[1];
                b[2 * p + 1][0] = r4[2]; b[2 * p + 1][1] = r4[3];
            }
#pragma unroll
            for (int mi = 0; mi < 2; mi++)
#pragma unroll
                for (int nj = 0; nj < 4; nj++)
                    mma16816(acc[mi][nj], a[mi], b[nj]);
        }
        __syncthreads();
    }
#pragma unroll
    for (int mi = 0; mi < 2; mi++) {
        int q = q0 + wm + mi * 16 + (lane >> 2);
#pragma unroll
        for (int nj = 0; nj < 4; nj++) {
            int c = h * 64 + wn + nj * 8 + 2 * (lane & 3);
            *(float2*)(g_attn + ((size_t)n * Ss + q) * Cc + c) =
                make_float2(acc[mi][nj][0], acc[mi][nj][1]);
            *(float2*)(g_attn + ((size_t)n * Ss + q + 8) * Cc + c) =
                make_float2(acc[mi][nj][2], acc[mi][nj][3]);
        }
    }
}

// ---------------- MLP GEMMs (fp32 SIMT) ----------------
template <int MODE>
__global__ __launch_bounds__(128) void k_mlp(const float* __restrict__ W,
                                             const float* __restrict__ bias) {
    int m0 = blockIdx.x * 128;
    int n0 = blockIdx.y * 64;
    const float* A = (MODE == 0) ? g_u : g_h1;

    __shared__ float As[16][128];
    __shared__ float Bs[16][64];
    float acc[8][8] = {};
    int tid = threadIdx.x;
    int tq = tid >> 3, td = tid & 7;

    for (int kb = 0; kb < Cc; kb += 16) {
#pragma unroll
        for (int i = 0; i < 4; i++) {
            int idx = tid + i * 128;
            int r = idx >> 2, c4 = idx & 3;
            float4 v = *(const float4*)(A + (size_t)(m0 + r) * Cc + kb + c4 * 4);
            As[c4 * 4 + 0][r] = v.x; As[c4 * 4 + 1][r] = v.y;
            As[c4 * 4 + 2][r] = v.z; As[c4 * 4 + 3][r] = v.w;
        }
#pragma unroll
        for (int i = 0; i < 2; i++) {
            int idx = tid + i * 128;
            int r = idx >> 4, c4 = idx & 15;
            *(float4*)&Bs[r][c4 * 4] = *(const float4*)(W + (size_t)(kb + r) * Cc + n0 + c4 * 4);
        }
        __syncthreads();
#pragma unroll
        for (int kk = 0; kk < 16; kk++) {
            float a[8], bb[8];
            *(float4*)a       = *(const float4*)&As[kk][tq * 8];
            *(float4*)(a + 4) = *(const float4*)&As[kk][tq * 8 + 4];
            *(float4*)bb       = *(const float4*)&Bs[kk][td * 8];
            *(float4*)(bb + 4) = *(const float4*)&Bs[kk][td * 8 + 4];
#pragma unroll
            for (int i = 0; i < 8; i++)
#pragma unroll
                for (int j = 0; j < 8; j++)
                    acc[i][j] = fmaf(a[i], bb[j], acc[i][j]);
        }
        __syncthreads();
    }
#pragma unroll
    for (int i = 0; i < 8; i++) {
        int row = m0 + tq * 8 + i;
        float vals[8];
#pragma unroll
        for (int j = 0; j < 8; j++) {
            int col = n0 + td * 8 + j;
            float val = acc[i][j] + bias[col];
            if (MODE == 0) {
                val = 0.5f * val * (1.0f + erff(val * 0.70710678118654752f));
            } else {
                val += g_attn[(size_t)row * Cc + col];
            }
            vals[j] = val;
        }
        size_t o = (size_t)row * Cc + n0 + td * 8;
        float* Out = (MODE == 0) ? g_h1 : g_o;
        *(float4*)(Out + o)     = make_float4(vals[0], vals[1], vals[2], vals[3]);
        *(float4*)(Out + o + 4) = make_float4(vals[4], vals[5], vals[6], vals[7]);
    }
}

// ---------------- launch ----------------
extern "C" void kernel_launch(void* const* d_in, const int* in_sizes, int n_in,
                              void* d_out, int out_size) {
    const float* x     = (const float*)d_in[0];
    const float* ln1_w = (const float*)d_in[1];
    const float* ln1_b = (const float*)d_in[2];
    const float* WQ    = (const float*)d_in[3];
    const float* WK    = (const float*)d_in[4];
    const float* WV    = (const float*)d_in[5];
    const float* ln2_w = (const float*)d_in[6];
    const float* ln2_b = (const float*)d_in[7];
    const float* W1    = (const float*)d_in[8];
    const float* b1    = (const float*)d_in[9];
    const float* W2    = (const float*)d_in[10];
    const float* b2    = (const float*)d_in[11];
    float* out = (float*)d_out;

    dim3 tb(32, 8);
    k_transpose_in<<<dim3(Ss / 32, Cc / 32, Nb), tb>>>(x);
    k_ln<0><<<Nb * Ss, 256>>>(ln1_w, ln1_b);

    k_qkv<<<dim3(Ss / 128, 12, Nb), 256>>>(WQ, WK, WV);

    k_yt<<<dim3(Ss / 128, Ss / 128, NH), 256>>>();
    k_rowstats<<<NH * Ss, 256>>>();
    k_attn<<<dim3(Ss / 128, NH), 256>>>();

    k_ln<1><<<Nb * Ss, 256>>>(ln2_w, ln2_b);
    k_mlp<0><<<dim3(64, 4), 128>>>(W1, b1);
    k_mlp<1><<<dim3(64, 4), 128>>>(W2, b2);

    k_transpose_out<<<dim3(Ss / 32, Cc / 32, Nb), tb>>>(out);
}

// round 4
// speedup vs baseline: 4.4064x; 1.5363x over previous
#include <cuda_runtime.h>
#include <cuda_fp16.h>
#include <cstdint>
#include <stdint.h>
#include <math.h>

// ---------------- problem constants ----------------
constexpr int Nb = 2;
constexpr int Cc = 256;
constexpr int Ss = 4096;
constexpr int Hh = 4;
constexpr int Dh = 64;
constexpr int NH = Nb * Hh;
constexpr float EPSV = 1e-5f;
constexpr float SCALE = 1.0f / 64.0f;

// ---------------- device scratch ----------------
__device__ float  g_r    [Nb * Ss * Cc];
__device__ __half g_normh[Nb * Ss * Cc];
__device__ __half g_Qh   [NH * Ss * Dh];   // pre-scaled by SCALE
__device__ __half g_Kh   [NH * Ss * Dh];
__device__ __half g_Vh   [NH * Ss * Dh];
__device__ float2 g_st   [NH * Ss];        // per-k (max, 1/sumexp)
__device__ float  g_attn [Nb * Ss * Cc];
__device__ float  g_u    [Nb * Ss * Cc];
__device__ float  g_h1   [Nb * Ss * Cc];
__device__ float  g_o    [Nb * Ss * Cc];

// ---------------- helpers ----------------
__device__ __forceinline__ unsigned smem_u32(const void* p) {
    return (unsigned)__cvta_generic_to_shared(p);
}
__device__ __forceinline__ void ldmx4(unsigned* r, unsigned a) {
    asm volatile("ldmatrix.sync.aligned.m8n8.x4.shared.b16 {%0,%1,%2,%3},[%4];"
                 : "=r"(r[0]), "=r"(r[1]), "=r"(r[2]), "=r"(r[3]) : "r"(a));
}
__device__ __forceinline__ void ldmx4t(unsigned* r, unsigned a) {
    asm volatile("ldmatrix.sync.aligned.m8n8.x4.trans.shared.b16 {%0,%1,%2,%3},[%4];"
                 : "=r"(r[0]), "=r"(r[1]), "=r"(r[2]), "=r"(r[3]) : "r"(a));
}
__device__ __forceinline__ void mma16816(float* c, const unsigned* a, const unsigned* b) {
    asm volatile(
        "mma.sync.aligned.m16n8k16.row.col.f32.f16.f16.f32 "
        "{%0,%1,%2,%3},{%4,%5,%6,%7},{%8,%9},{%0,%1,%2,%3};"
        : "+f"(c[0]), "+f"(c[1]), "+f"(c[2]), "+f"(c[3])
        : "r"(a[0]), "r"(a[1]), "r"(a[2]), "r"(a[3]), "r"(b[0]), "r"(b[1]));
}
__device__ __forceinline__ void cpa16(unsigned dst, const void* src) {
    asm volatile("cp.async.ca.shared.global [%0], [%1], 16;" :: "r"(dst), "l"(src));
}
__device__ __forceinline__ void cpa_commit() {
    asm volatile("cp.async.commit_group;");
}
template <int N>
__device__ __forceinline__ void cpa_wait() {
    asm volatile("cp.async.wait_group %0;" :: "n"(N));
}

// ---------------- transpose in: x[n,c,s] -> r[n,s,c] ----------------
__global__ void k_transpose_in(const float* __restrict__ x) {
    __shared__ float t[32][33];
    int n = blockIdx.z;
    int s0 = blockIdx.x * 32, c0 = blockIdx.y * 32;
    int tx = threadIdx.x, ty = threadIdx.y;
#pragma unroll
    for (int i = 0; i < 4; i++)
        t[ty + 8 * i][tx] = x[((size_t)(n * Cc + c0 + ty + 8 * i)) * Ss + s0 + tx];
    __syncthreads();
#pragma unroll
    for (int i = 0; i < 4; i++)
        g_r[((size_t)(n * Ss + s0 + ty + 8 * i)) * Cc + c0 + tx] = t[tx][ty + 8 * i];
}

// ---------------- transpose out ----------------
__global__ void k_transpose_out(float* __restrict__ out) {
    __shared__ float t[32][33];
    int n = blockIdx.z;
    int s0 = blockIdx.x * 32, c0 = blockIdx.y * 32;
    int tx = threadIdx.x, ty = threadIdx.y;
#pragma unroll
    for (int i = 0; i < 4; i++)
        t[ty + 8 * i][tx] = g_o[((size_t)(n * Ss + s0 + ty + 8 * i)) * Cc + c0 + tx];
    __syncthreads();
#pragma unroll
    for (int i = 0; i < 4; i++)
        out[((size_t)(n * Cc + c0 + ty + 8 * i)) * Ss + s0 + tx] = t[tx][ty + 8 * i];
}

// ---------------- LayerNorm ----------------
template <int MODE>
__global__ void k_ln(const float* __restrict__ w, const float* __restrict__ b) {
    int row = blockIdx.x;
    int t = threadIdx.x;
    size_t idx = (size_t)row * Cc + t;
    float v = (MODE == 0) ? g_r[idx] : (g_attn[idx] + g_r[idx]);

    float s1 = v, s2 = v * v;
#pragma unroll
    for (int o = 16; o; o >>= 1) {
        s1 += __shfl_xor_sync(0xffffffffu, s1, o);
        s2 += __shfl_xor_sync(0xffffffffu, s2, o);
    }
    __shared__ float sm1[8], sm2[8];
    __shared__ float mb, rb;
    int w8 = t >> 5, lane = t & 31;
    if (!lane) { sm1[w8] = s1; sm2[w8] = s2; }
    __syncthreads();
    if (t == 0) {
        float a = 0.f, q = 0.f;
#pragma unroll
        for (int i = 0; i < 8; i++) { a += sm1[i]; q += sm2[i]; }
        float mean = a * (1.0f / Cc);
        float var = q * (1.0f / Cc) - mean * mean;
        mb = mean;
        rb = rsqrtf(var + EPSV);
    }
    __syncthreads();
    float o = (v - mb) * rb * w[t] + b[t];
    if (MODE == 0) g_normh[idx] = __float2half(o);
    else g_u[idx] = o;
}

// ---------------- QKV projection, fp16 mma (Q pre-scaled) ----------------
__global__ __launch_bounds__(256) void k_qkv(const float* __restrict__ WQ,
                                             const float* __restrict__ WK,
                                             const float* __restrict__ WV) {
    int which = blockIdx.y >> 2;
    int h = blockIdx.y & 3;
    int n = blockIdx.z;
    int m0 = blockIdx.x * 128;
    const float* W = (which == 0 ? WQ : which == 1 ? WK : WV) + h * Cc * Dh;
    __half* Out = (which == 0 ? g_Qh : which == 1 ? g_Kh : g_Vh) + (size_t)(n * 4 + h) * Ss * Dh;
    const __half* A = g_normh + (size_t)n * Ss * Cc;
    float oscale = (which == 0) ? SCALE : 1.0f;

    __shared__ __half As[128][88];
    __shared__ __half Bs[64][88];
    int tid = threadIdx.x, lane = tid & 31, wid = tid >> 5;
    int wm = (wid >> 1) * 32;
    int wn = (wid & 1) * 32;
    float acc[2][4][4] = {};

    for (int kb = 0; kb < Cc; kb += 64) {
#pragma unroll
        for (int i = 0; i < 4; i++) {
            int idx = tid + i * 256;
            int r = idx >> 3, c8 = idx & 7;
            *(float4*)&As[r][c8 * 8] = *(const float4*)(A + (size_t)(m0 + r) * Cc + kb + c8 * 8);
        }
#pragma unroll
        for (int i = 0; i < 4; i++) {
            int idx = tid + i * 256;
            int r = idx >> 4, c4 = idx & 15;
            float4 v = *(const float4*)(W + (size_t)(kb + r) * Dh + c4 * 4);
            __half2* d = (__half2*)&Bs[r][c4 * 4];
            d[0] = __floats2half2_rn(v.x, v.y);
            d[1] = __floats2half2_rn(v.z, v.w);
        }
        __syncthreads();
#pragma unroll
        for (int kk = 0; kk < 64; kk += 16) {
            unsigned a[2][4], b[4][2];
#pragma unroll
            for (int mi = 0; mi < 2; mi++)
                ldmx4(a[mi], smem_u32(&As[wm + mi * 16 + (lane & 15)][kk + (lane >> 4) * 8]));
#pragma unroll
            for (int p = 0; p < 2; p++) {
                unsigned r4[4];
                ldmx4t(r4, smem_u32(&Bs[kk + (lane & 7) + ((lane >> 3) & 1) * 8]
                                       [wn + p * 16 + (lane >> 4) * 8]));
                b[2 * p][0] = r4[0]; b[2 * p][1] = r4[1];
                b[2 * p + 1][0] = r4[2]; b[2 * p + 1][1] = r4[3];
            }
#pragma unroll
            for (int mi = 0; mi < 2; mi++)
#pragma unroll
                for (int nj = 0; nj < 4; nj++)
                    mma16816(acc[mi][nj], a[mi], b[nj]);
        }
        __syncthreads();
    }
#pragma unroll
    for (int mi = 0; mi < 2; mi++) {
        int r = m0 + wm + mi * 16 + (lane >> 2);
#pragma unroll
        for (int nj = 0; nj < 4; nj++) {
            int c = wn + nj * 8 + 2 * (lane & 3);
            *(__half2*)(Out + (size_t)r * Dh + c) =
                __floats2half2_rn(acc[mi][nj][0] * oscale, acc[mi][nj][1] * oscale);
            *(__half2*)(Out + (size_t)(r + 8) * Dh + c) =
                __floats2half2_rn(acc[mi][nj][2] * oscale, acc[mi][nj][3] * oscale);
        }
    }
}

// ---------------- pass 1: per-k softmax stats, no Y materialization ----------------
// grid (32 ktiles, 8 nh), block 256 = 8 warps (4m x 2n), warp tile 32k x 64q
__global__ __launch_bounds__(256) void k_stats() {
    int nh = blockIdx.y;
    int k0 = blockIdx.x * 128;
    const __half* Kp = g_Kh + (size_t)nh * Ss * Dh;
    const __half* Qp = g_Qh + (size_t)nh * Ss * Dh;

    __shared__ __half As[128][72];      // K tile [k][d]
    __shared__ __half Bs[2][128][72];   // Q tiles double buffered [q][d]
    __shared__ float2 sred[2][128];

    int tid = threadIdx.x, lane = tid & 31, wid = tid >> 5;
    int wm = (wid >> 1) * 32;   // 2 m16 tiles (k rows)
    int wn = (wid & 1) * 64;    // 8 n8 tiles (q cols)

    // load K tile (plain), issue first Q tile (cp.async)
#pragma unroll
    for (int i = 0; i < 4; i++) {
        int idx = tid + i * 256;
        int r = idx >> 3, c8 = idx & 7;
        *(float4*)&As[r][c8 * 8] = *(const float4*)(Kp + (size_t)(k0 + r) * Dh + c8 * 8);
    }
#pragma unroll
    for (int i = 0; i < 4; i++) {
        int idx = tid + i * 256;
        int r = idx >> 3, c8 = idx & 7;
        cpa16(smem_u32(&Bs[0][r][c8 * 8]), Qp + (size_t)r * Dh + c8 * 8);
    }
    cpa_commit();
    __syncthreads();

    // hoist A fragments (K tile fixed for whole kernel)
    unsigned a[2][4][4];
#pragma unroll
    for (int mi = 0; mi < 2; mi++)
#pragma unroll
        for (int t = 0; t < 4; t++)
            ldmx4(a[mi][t], smem_u32(&As[wm + mi * 16 + (lane & 15)][t * 16 + (lane >> 4) * 8]));

    float m_run[4] = {-1e30f, -1e30f, -1e30f, -1e30f};
    float s_run[4] = {0.f, 0.f, 0.f, 0.f};

    for (int c = 0; c < 32; c++) {
        __syncthreads();   // all warps done with buffer (c+1)&1 from iter c-1
        if (c + 1 < 32) {
            int q1 = (c + 1) * 128;
            int bufn = (c + 1) & 1;
#pragma unroll
            for (int i = 0; i < 4; i++) {
                int idx = tid + i * 256;
                int r = idx >> 3, c8 = idx & 7;
                cpa16(smem_u32(&Bs[bufn][r][c8 * 8]), Qp + (size_t)(q1 + r) * Dh + c8 * 8);
            }
            cpa_commit();
            cpa_wait<1>();
        } else {
            cpa_wait<0>();
        }
        __syncthreads();
        int buf = c & 1;

        float acc[2][8][4] = {};
#pragma unroll
        for (int t = 0; t < 4; t++) {
            unsigned b[8][2];
#pragma unroll
            for (int p = 0; p < 4; p++) {
                unsigned r4[4];
                ldmx4(r4, smem_u32(&Bs[buf][wn + p * 16 + (lane & 7) + (lane >> 4) * 8]
                                         [t * 16 + ((lane >> 3) & 1) * 8]));
                b[2 * p][0] = r4[0]; b[2 * p][1] = r4[1];
                b[2 * p + 1][0] = r4[2]; b[2 * p + 1][1] = r4[3];
            }
#pragma unroll
            for (int mi = 0; mi < 2; mi++)
#pragma unroll
                for (int nj = 0; nj < 8; nj++)
                    mma16816(acc[mi][nj], a[mi][t], b[nj]);
        }
        // online (max,sum) update per row-slot
#pragma unroll
        for (int mi = 0; mi < 2; mi++)
#pragma unroll
            for (int half = 0; half < 2; half++) {
                int slot = mi * 2 + half;
                float tm = -1e30f;
#pragma unroll
                for (int nj = 0; nj < 8; nj++)
                    tm = fmaxf(tm, fmaxf(acc[mi][nj][2 * half], acc[mi][nj][2 * half + 1]));
                float nm = fmaxf(m_run[slot], tm);
                float s = 0.f;
#pragma unroll
                for (int nj = 0; nj < 8; nj++)
                    s += __expf(acc[mi][nj][2 * half] - nm) +
                         __expf(acc[mi][nj][2 * half + 1] - nm);
                s_run[slot] = s_run[slot] * __expf(m_run[slot] - nm) + s;
                m_run[slot] = nm;
            }
    }

    // combine across lane quads (same row, different q columns)
#pragma unroll
    for (int off = 1; off <= 2; off <<= 1) {
#pragma unroll
        for (int slot = 0; slot < 4; slot++) {
            float om = __shfl_xor_sync(0xffffffffu, m_run[slot], off);
            float os = __shfl_xor_sync(0xffffffffu, s_run[slot], off);
            float nm = fmaxf(m_run[slot], om);
            s_run[slot] = s_run[slot] * __expf(m_run[slot] - nm) + os * __expf(om - nm);
            m_run[slot] = nm;
        }
    }
    __syncthreads();
    if ((lane & 3) == 0) {
#pragma unroll
        for (int mi = 0; mi < 2; mi++)
#pragma unroll
            for (int half = 0; half < 2; half++) {
                int slot = mi * 2 + half;
                int row = wm + mi * 16 + half * 8 + (lane >> 2);
                sred[wid & 1][row] = make_float2(m_run[slot], s_run[slot]);
            }
    }
    __syncthreads();
    if (tid < 128) {
        float2 A0 = sred[0][tid], B0 = sred[1][tid];
        float nm = fmaxf(A0.x, B0.x);
        float s = A0.y * __expf(A0.x - nm) + B0.y * __expf(B0.x - nm);
        g_st[nh * Ss + k0 + tid] = make_float2(nm, 1.0f / s);
    }
}

// ---------------- pass 2: flash-style attn = exp-norm(Q K^T) V ----------------
// grid (32 qtiles, 8 nh), block 256 = 8 warps, warp tile 16q x 64; k chunks of 64
__global__ __launch_bounds__(256) void k_flash() {
    int nh = blockIdx.y, n = nh >> 2, h = nh & 3;
    int q0 = blockIdx.x * 128;
    const __half* Qp = g_Qh + (size_t)nh * Ss * Dh;
    const __half* Kp = g_Kh + (size_t)nh * Ss * Dh;
    const __half* Vp = g_Vh + (size_t)nh * Ss * Dh;
    const float2* St = g_st + nh * Ss;

    __shared__ __half Qs[128][72];
    __shared__ __half Ks[2][64][72];
    __shared__ __half Vs[2][64][72];

    int tid = threadIdx.x, lane = tid & 31, wid = tid >> 5;
    int wm = wid * 16;

    // load Q tile (plain), issue first K/V chunk (cp.async)
#pragma unroll
    for (int i = 0; i < 4; i++) {
        int idx = tid + i * 256;
        int r = idx >> 3, c8 = idx & 7;
        *(float4*)&Qs[r][c8 * 8] = *(const float4*)(Qp + (size_t)(q0 + r) * Dh + c8 * 8);
    }
#pragma unroll
    for (int i = 0; i < 2; i++) {
        int idx = tid + i * 256;
        int r = idx >> 3, c8 = idx & 7;
        cpa16(smem_u32(&Ks[0][r][c8 * 8]), Kp + (size_t)r * Dh + c8 * 8);
        cpa16(smem_u32(&Vs[0][r][c8 * 8]), Vp + (size_t)r * Dh + c8 * 8);
    }
    cpa_commit();
    __syncthreads();

    // hoist Q fragments
    unsigned aq[4][4];
#pragma unroll
    for (int t = 0; t < 4; t++)
        ldmx4(aq[t], smem_u32(&Qs[wm + (lane & 15)][t * 16 + (lane >> 4) * 8]));

    float accO[8][4] = {};

    for (int c = 0; c < 64; c++) {
        __syncthreads();
        if (c + 1 < 64) {
            int kb1 = (c + 1) * 64;
            int bufn = (c + 1) & 1;
#pragma unroll
            for (int i = 0; i < 2; i++) {
                int idx = tid + i * 256;
                int r = idx >> 3, c8 = idx & 7;
                cpa16(smem_u32(&Ks[bufn][r][c8 * 8]), Kp + (size_t)(kb1 + r) * Dh + c8 * 8);
                cpa16(smem_u32(&Vs[bufn][r][c8 * 8]), Vp + (size_t)(kb1 + r) * Dh + c8 * 8);
            }
            cpa_commit();
            cpa_wait<1>();
        } else {
            cpa_wait<0>();
        }
        __syncthreads();
        int buf = c & 1;
        int kb = c * 64;

        // S = Q K^T  [16q x 64k] per warp
        float accS[8][4] = {};
#pragma unroll
        for (int t = 0; t < 4; t++) {
            unsigned b[8][2];
#pragma unroll
            for (int p = 0; p < 4; p++) {
                unsigned r4[4];
                ldmx4(r4, smem_u32(&Ks[buf][p * 16 + (lane & 7) + (lane >> 4) * 8]
                                         [t * 16 + ((lane >> 3) & 1) * 8]));
                b[2 * p][0] = r4[0]; b[2 * p][1] = r4[1];
                b[2 * p + 1][0] = r4[2]; b[2 * p + 1][1] = r4[3];
            }
#pragma unroll
            for (int nj = 0; nj < 8; nj++)
                mma16816(accS[nj], aq[t], b[nj]);
        }

        // P = exp(S - m_k)*inv_k, packed straight into A fragments
        unsigned ap[4][4];
#pragma unroll
        for (int nj = 0; nj < 8; nj++) {
            int col = kb + nj * 8 + 2 * (lane & 3);
            float2 st0 = St[col];
            float2 st1 = St[col + 1];
            float p0 = __expf(accS[nj][0] - st0.x) * st0.y;
            float p1 = __expf(accS[nj][1] - st1.x) * st1.y;
            float p2 = __expf(accS[nj][2] - st0.x) * st0.y;
            float p3 = __expf(accS[nj][3] - st1.x) * st1.y;
            int t = nj >> 1, w2 = (nj & 1) * 2;
            __half2 h0 = __floats2half2_rn(p0, p1);
            __half2 h1 = __floats2half2_rn(p2, p3);
            ap[t][w2]     = *(unsigned*)&h0;
            ap[t][w2 + 1] = *(unsigned*)&h1;
        }

        // O += P V   [16q x 64d] per warp
#pragma unroll
        for (int t = 0; t < 4; t++) {
            unsigned bv[8][2];
#pragma unroll
            for (int p = 0; p < 4; p++) {
                unsigned r4[4];
                ldmx4t(r4, smem_u32(&Vs[buf][t * 16 + (lane & 7) + ((lane >> 3) & 1) * 8]
                                          [p * 16 + (lane >> 4) * 8]));
                bv[2 * p][0] = r4[0]; bv[2 * p][1] = r4[1];
                bv[2 * p + 1][0] = r4[2]; bv[2 * p + 1][1] = r4[3];
            }
#pragma unroll
            for (int dj = 0; dj < 8; dj++)
                mma16816(accO[dj], ap[t], bv[dj]);
        }
    }

    // write attn_cat[n, q, h*64 + d]
#pragma unroll
    for (int dj = 0; dj < 8; dj++) {
        int q = q0 + wm + (lane >> 2);
        int col = h * 64 + dj * 8 + 2 * (lane & 3);
        *(float2*)(g_attn + ((size_t)n * Ss + q) * Cc + col) =
            make_float2(accO[dj][0], accO[dj][1]);
        *(float2*)(g_attn + ((size_t)n * Ss + q + 8) * Cc + col) =
            make_float2(accO[dj][2], accO[dj][3]);
    }
}

// ---------------- MLP GEMMs (fp32 SIMT) ----------------
template <int MODE>
__global__ __launch_bounds__(128) void k_mlp(const float* __restrict__ W,
                                             const float* __restrict__ bias) {
    int m0 = blockIdx.x * 128;
    int n0 = blockIdx.y * 64;
    const float* A = (MODE == 0) ? g_u : g_h1;

    __shared__ float As[16][128];
    __shared__ float Bs[16][64];
    float acc[8][8] = {};
    int tid = threadIdx.x;
    int tq = tid >> 3, td = tid & 7;

    for (int kb = 0; kb < Cc; kb += 16) {
#pragma unroll
        for (int i = 0; i < 4; i++) {
            int idx = tid + i * 128;
            int r = idx >> 2, c4 = idx & 3;
            float4 v = *(const float4*)(A + (size_t)(m0 + r) * Cc + kb + c4 * 4);
            As[c4 * 4 + 0][r] = v.x; As[c4 * 4 + 1][r] = v.y;
            As[c4 * 4 + 2][r] = v.z; As[c4 * 4 + 3][r] = v.w;
        }
#pragma unroll
        for (int i = 0; i < 2; i++) {
            int idx = tid + i * 128;
            int r = idx >> 4, c4 = idx & 15;
            *(float4*)&Bs[r][c4 * 4] = *(const float4*)(W + (size_t)(kb + r) * Cc + n0 + c4 * 4);
        }
        __syncthreads();
#pragma unroll
        for (int kk = 0; kk < 16; kk++) {
            float a[8], bb[8];
            *(float4*)a       = *(const float4*)&As[kk][tq * 8];
            *(float4*)(a + 4) = *(const float4*)&As[kk][tq * 8 + 4];
            *(float4*)bb       = *(const float4*)&Bs[kk][td * 8];
            *(float4*)(bb + 4) = *(const float4*)&Bs[kk][td * 8 + 4];
#pragma unroll
            for (int i = 0; i < 8; i++)
#pragma unroll
                for (int j = 0; j < 8; j++)
                    acc[i][j] = fmaf(a[i], bb[j], acc[i][j]);
        }
        __syncthreads();
    }
#pragma unroll
    for (int i = 0; i < 8; i++) {
        int row = m0 + tq * 8 + i;
        float vals[8];
#pragma unroll
        for (int j = 0; j < 8; j++) {
            int col = n0 + td * 8 + j;
            float val = acc[i][j] + bias[col];
            if (MODE == 0) {
                val = 0.5f * val * (1.0f + erff(val * 0.70710678118654752f));
            } else {
                val += g_attn[(size_t)row * Cc + col];
            }
            vals[j] = val;
        }
        size_t o = (size_t)row * Cc + n0 + td * 8;
        float* Out = (MODE == 0) ? g_h1 : g_o;
        *(float4*)(Out + o)     = make_float4(vals[0], vals[1], vals[2], vals[3]);
        *(float4*)(Out + o + 4) = make_float4(vals[4], vals[5], vals[6], vals[7]);
    }
}

// ---------------- launch ----------------
extern "C" void kernel_launch(void* const* d_in, const int* in_sizes, int n_in,
                              void* d_out, int out_size) {
    const float* x     = (const float*)d_in[0];
    const float* ln1_w = (const float*)d_in[1];
    const float* ln1_b = (const float*)d_in[2];
    const float* WQ    = (const float*)d_in[3];
    const float* WK    = (const float*)d_in[4];
    const float* WV    = (const float*)d_in[5];
    const float* ln2_w = (const float*)d_in[6];
    const float* ln2_b = (const float*)d_in[7];
    const float* W1    = (const float*)d_in[8];
    const float* b1    = (const float*)d_in[9];
    const float* W2    = (const float*)d_in[10];
    const float* b2    = (const float*)d_in[11];
    float* out = (float*)d_out;

    dim3 tb(32, 8);
    k_transpose_in<<<dim3(Ss / 32, Cc / 32, Nb), tb>>>(x);
    k_ln<0><<<Nb * Ss, 256>>>(ln1_w, ln1_b);

    k_qkv<<<dim3(Ss / 128, 12, Nb), 256>>>(WQ, WK, WV);

    k_stats<<<dim3(Ss / 128, NH), 256>>>();
    k_flash<<<dim3(Ss / 128, NH), 256>>>();

    k_ln<1><<<Nb * Ss, 256>>>(ln2_w, ln2_b);
    k_mlp<0><<<dim3(64, 4), 128>>>(W1, b1);
    k_mlp<1><<<dim3(64, 4), 128>>>(W2, b2);

    k_transpose_out<<<dim3(Ss / 32, Cc / 32, Nb), tb>>>(out);
}

// round 5
// speedup vs baseline: 5.5389x; 1.2570x over previous
#include <cuda_runtime.h>
#include <cuda_fp16.h>
#include <cstdint>
#include <stdint.h>
#include <math.h>

// ---------------- problem constants ----------------
constexpr int Nb = 2;
constexpr int Cc = 256;
constexpr int Ss = 4096;
constexpr int Hh = 4;
constexpr int Dh = 64;
constexpr int NH = Nb * Hh;
constexpr float EPSV = 1e-5f;
constexpr float SCALE = 1.0f / 64.0f;
constexpr int QSPLIT = 4;   // k_stats q-range splits
constexpr int KSPLIT = 4;   // k_flash k-range splits

// ---------------- device scratch ----------------
__device__ float  g_r    [Nb * Ss * Cc];
__device__ __half g_normh[Nb * Ss * Cc];
__device__ __half g_Qh   [NH * Ss * Dh];   // pre-scaled by SCALE
__device__ __half g_Kh   [NH * Ss * Dh];
__device__ __half g_Vh   [NH * Ss * Dh];
__device__ float2 g_stp  [QSPLIT * NH * Ss];  // partial (max, sumexp)
__device__ float2 g_st   [NH * Ss];           // final (max, 1/sumexp)
__device__ float  g_po   [KSPLIT * NH * Ss * Dh];  // partial O
__device__ float  g_attn [Nb * Ss * Cc];
__device__ __half g_uh   [Nb * Ss * Cc];
__device__ __half g_h1h  [Nb * Ss * Cc];
__device__ __half g_W1h  [Cc * Cc];
__device__ __half g_W2h  [Cc * Cc];
__device__ float  g_o    [Nb * Ss * Cc];

// ---------------- helpers ----------------
__device__ __forceinline__ unsigned smem_u32(const void* p) {
    return (unsigned)__cvta_generic_to_shared(p);
}
__device__ __forceinline__ void ldmx4(unsigned* r, unsigned a) {
    asm volatile("ldmatrix.sync.aligned.m8n8.x4.shared.b16 {%0,%1,%2,%3},[%4];"
                 : "=r"(r[0]), "=r"(r[1]), "=r"(r[2]), "=r"(r[3]) : "r"(a));
}
__device__ __forceinline__ void ldmx4t(unsigned* r, unsigned a) {
    asm volatile("ldmatrix.sync.aligned.m8n8.x4.trans.shared.b16 {%0,%1,%2,%3},[%4];"
                 : "=r"(r[0]), "=r"(r[1]), "=r"(r[2]), "=r"(r[3]) : "r"(a));
}
__device__ __forceinline__ void mma16816(float* c, const unsigned* a, const unsigned* b) {
    asm volatile(
        "mma.sync.aligned.m16n8k16.row.col.f32.f16.f16.f32 "
        "{%0,%1,%2,%3},{%4,%5,%6,%7},{%8,%9},{%0,%1,%2,%3};"
        : "+f"(c[0]), "+f"(c[1]), "+f"(c[2]), "+f"(c[3])
        : "r"(a[0]), "r"(a[1]), "r"(a[2]), "r"(a[3]), "r"(b[0]), "r"(b[1]));
}
__device__ __forceinline__ void cpa16(unsigned dst, const void* src) {
    asm volatile("cp.async.ca.shared.global [%0], [%1], 16;" :: "r"(dst), "l"(src));
}
__device__ __forceinline__ void cpa_commit() {
    asm volatile("cp.async.commit_group;");
}
template <int N>
__device__ __forceinline__ void cpa_wait() {
    asm volatile("cp.async.wait_group %0;" :: "n"(N));
}

// ---------------- transpose in: x[n,c,s] -> r[n,s,c] ----------------
__global__ void k_transpose_in(const float* __restrict__ x) {
    __shared__ float t[32][33];
    int n = blockIdx.z;
    int s0 = blockIdx.x * 32, c0 = blockIdx.y * 32;
    int tx = threadIdx.x, ty = threadIdx.y;
#pragma unroll
    for (int i = 0; i < 4; i++)
        t[ty + 8 * i][tx] = x[((size_t)(n * Cc + c0 + ty + 8 * i)) * Ss + s0 + tx];
    __syncthreads();
#pragma unroll
    for (int i = 0; i < 4; i++)
        g_r[((size_t)(n * Ss + s0 + ty + 8 * i)) * Cc + c0 + tx] = t[tx][ty + 8 * i];
}

// ---------------- transpose out ----------------
__global__ void k_transpose_out(float* __restrict__ out) {
    __shared__ float t[32][33];
    int n = blockIdx.z;
    int s0 = blockIdx.x * 32, c0 = blockIdx.y * 32;
    int tx = threadIdx.x, ty = threadIdx.y;
#pragma unroll
    for (int i = 0; i < 4; i++)
        t[ty + 8 * i][tx] = g_o[((size_t)(n * Ss + s0 + ty + 8 * i)) * Cc + c0 + tx];
    __syncthreads();
#pragma unroll
    for (int i = 0; i < 4; i++)
        out[((size_t)(n * Cc + c0 + ty + 8 * i)) * Ss + s0 + tx] = t[tx][ty + 8 * i];
}

// ---------------- weight fp32 -> fp16 ----------------
__global__ void k_cvtw(const float* __restrict__ W1, const float* __restrict__ W2) {
    int i = blockIdx.x * 256 + threadIdx.x;
    g_W1h[i] = __float2half(W1[i]);
    g_W2h[i] = __float2half(W2[i]);
}

// ---------------- LayerNorm ----------------
// MODE 0: g_normh = half(LN(g_r));  MODE 1: g_uh = half(LN(g_attn + g_r))
template <int MODE>
__global__ void k_ln(const float* __restrict__ w, const float* __restrict__ b) {
    int row = blockIdx.x;
    int t = threadIdx.x;
    size_t idx = (size_t)row * Cc + t;
    float v = (MODE == 0) ? g_r[idx] : (g_attn[idx] + g_r[idx]);

    float s1 = v, s2 = v * v;
#pragma unroll
    for (int o = 16; o; o >>= 1) {
        s1 += __shfl_xor_sync(0xffffffffu, s1, o);
        s2 += __shfl_xor_sync(0xffffffffu, s2, o);
    }
    __shared__ float sm1[8], sm2[8];
    __shared__ float mb, rb;
    int w8 = t >> 5, lane = t & 31;
    if (!lane) { sm1[w8] = s1; sm2[w8] = s2; }
    __syncthreads();
    if (t == 0) {
        float a = 0.f, q = 0.f;
#pragma unroll
        for (int i = 0; i < 8; i++) { a += sm1[i]; q += sm2[i]; }
        float mean = a * (1.0f / Cc);
        float var = q * (1.0f / Cc) - mean * mean;
        mb = mean;
        rb = rsqrtf(var + EPSV);
    }
    __syncthreads();
    float o = (v - mb) * rb * w[t] + b[t];
    if (MODE == 0) g_normh[idx] = __float2half(o);
    else g_uh[idx] = __float2half(o);
}

// ---------------- QKV projection, fp16 mma (Q pre-scaled) ----------------
__global__ __launch_bounds__(256) void k_qkv(const float* __restrict__ WQ,
                                             const float* __restrict__ WK,
                                             const float* __restrict__ WV) {
    int which = blockIdx.y >> 2;
    int h = blockIdx.y & 3;
    int n = blockIdx.z;
    int m0 = blockIdx.x * 128;
    const float* W = (which == 0 ? WQ : which == 1 ? WK : WV) + h * Cc * Dh;
    __half* Out = (which == 0 ? g_Qh : which == 1 ? g_Kh : g_Vh) + (size_t)(n * 4 + h) * Ss * Dh;
    const __half* A = g_normh + (size_t)n * Ss * Cc;
    float oscale = (which == 0) ? SCALE : 1.0f;

    __shared__ __half As[128][88];
    __shared__ __half Bs[64][88];
    int tid = threadIdx.x, lane = tid & 31, wid = tid >> 5;
    int wm = (wid >> 1) * 32;
    int wn = (wid & 1) * 32;
    float acc[2][4][4] = {};

    for (int kb = 0; kb < Cc; kb += 64) {
#pragma unroll
        for (int i = 0; i < 4; i++) {
            int idx = tid + i * 256;
            int r = idx >> 3, c8 = idx & 7;
            *(float4*)&As[r][c8 * 8] = *(const float4*)(A + (size_t)(m0 + r) * Cc + kb + c8 * 8);
        }
#pragma unroll
        for (int i = 0; i < 4; i++) {
            int idx = tid + i * 256;
            int r = idx >> 4, c4 = idx & 15;
            float4 v = *(const float4*)(W + (size_t)(kb + r) * Dh + c4 * 4);
            __half2* d = (__half2*)&Bs[r][c4 * 4];
            d[0] = __floats2half2_rn(v.x, v.y);
            d[1] = __floats2half2_rn(v.z, v.w);
        }
        __syncthreads();
#pragma unroll
        for (int kk = 0; kk < 64; kk += 16) {
            unsigned a[2][4], b[4][2];
#pragma unroll
            for (int mi = 0; mi < 2; mi++)
                ldmx4(a[mi], smem_u32(&As[wm + mi * 16 + (lane & 15)][kk + (lane >> 4) * 8]));
#pragma unroll
            for (int p = 0; p < 2; p++) {
                unsigned r4[4];
                ldmx4t(r4, smem_u32(&Bs[kk + (lane & 7) + ((lane >> 3) & 1) * 8]
                                       [wn + p * 16 + (lane >> 4) * 8]));
                b[2 * p][0] = r4[0]; b[2 * p][1] = r4[1];
                b[2 * p + 1][0] = r4[2]; b[2 * p + 1][1] = r4[3];
            }
#pragma unroll
            for (int mi = 0; mi < 2; mi++)
#pragma unroll
                for (int nj = 0; nj < 4; nj++)
                    mma16816(acc[mi][nj], a[mi], b[nj]);
        }
        __syncthreads();
    }
#pragma unroll
    for (int mi = 0; mi < 2; mi++) {
        int r = m0 + wm + mi * 16 + (lane >> 2);
#pragma unroll
        for (int nj = 0; nj < 4; nj++) {
            int c = wn + nj * 8 + 2 * (lane & 3);
            *(__half2*)(Out + (size_t)r * Dh + c) =
                __floats2half2_rn(acc[mi][nj][0] * oscale, acc[mi][nj][1] * oscale);
            *(__half2*)(Out + (size_t)(r + 8) * Dh + c) =
                __floats2half2_rn(acc[mi][nj][2] * oscale, acc[mi][nj][3] * oscale);
        }
    }
}

// ---------------- pass 1: per-k partial softmax stats (q split) ----------------
// grid (32 ktiles, NH, QSPLIT), block 256 = 8 warps (4m x 2n)
__global__ __launch_bounds__(256) void k_stats() {
    int nh = blockIdx.y;
    int qs = blockIdx.z;
    int k0 = blockIdx.x * 128;
    const __half* Kp = g_Kh + (size_t)nh * Ss * Dh;
    const __half* Qp = g_Qh + (size_t)nh * Ss * Dh;
    constexpr int NITER = Ss / 128 / QSPLIT;   // 8
    int qbase = qs * (Ss / QSPLIT);

    __shared__ __half As[128][72];
    __shared__ __half Bs[2][128][72];
    __shared__ float2 sred[2][128];

    int tid = threadIdx.x, lane = tid & 31, wid = tid >> 5;
    int wm = (wid >> 1) * 32;
    int wn = (wid & 1) * 64;

#pragma unroll
    for (int i = 0; i < 4; i++) {
        int idx = tid + i * 256;
        int r = idx >> 3, c8 = idx & 7;
        *(float4*)&As[r][c8 * 8] = *(const float4*)(Kp + (size_t)(k0 + r) * Dh + c8 * 8);
    }
#pragma unroll
    for (int i = 0; i < 4; i++) {
        int idx = tid + i * 256;
        int r = idx >> 3, c8 = idx & 7;
        cpa16(smem_u32(&Bs[0][r][c8 * 8]), Qp + (size_t)(qbase + r) * Dh + c8 * 8);
    }
    cpa_commit();
    __syncthreads();

    unsigned a[2][4][4];
#pragma unroll
    for (int mi = 0; mi < 2; mi++)
#pragma unroll
        for (int t = 0; t < 4; t++)
            ldmx4(a[mi][t], smem_u32(&As[wm + mi * 16 + (lane & 15)][t * 16 + (lane >> 4) * 8]));

    float m_run[4] = {-1e30f, -1e30f, -1e30f, -1e30f};
    float s_run[4] = {0.f, 0.f, 0.f, 0.f};

    for (int c = 0; c < NITER; c++) {
        __syncthreads();
        if (c + 1 < NITER) {
            int q1 = qbase + (c + 1) * 128;
            int bufn = (c + 1) & 1;
#pragma unroll
            for (int i = 0; i < 4; i++) {
                int idx = tid + i * 256;
                int r = idx >> 3, c8 = idx & 7;
                cpa16(smem_u32(&Bs[bufn][r][c8 * 8]), Qp + (size_t)(q1 + r) * Dh + c8 * 8);
            }
            cpa_commit();
            cpa_wait<1>();
        } else {
            cpa_wait<0>();
        }
        __syncthreads();
        int buf = c & 1;

        float acc[2][8][4] = {};
#pragma unroll
        for (int t = 0; t < 4; t++) {
            unsigned b[8][2];
#pragma unroll
            for (int p = 0; p < 4; p++) {
                unsigned r4[4];
                ldmx4(r4, smem_u32(&Bs[buf][wn + p * 16 + (lane & 7) + (lane >> 4) * 8]
                                         [t * 16 + ((lane >> 3) & 1) * 8]));
                b[2 * p][0] = r4[0]; b[2 * p][1] = r4[1];
                b[2 * p + 1][0] = r4[2]; b[2 * p + 1][1] = r4[3];
            }
#pragma unroll
            for (int mi = 0; mi < 2; mi++)
#pragma unroll
                for (int nj = 0; nj < 8; nj++)
                    mma16816(acc[mi][nj], a[mi][t], b[nj]);
        }
#pragma unroll
        for (int mi = 0; mi < 2; mi++)
#pragma unroll
            for (int half = 0; half < 2; half++) {
                int slot = mi * 2 + half;
                float tm = -1e30f;
#pragma unroll
                for (int nj = 0; nj < 8; nj++)
                    tm = fmaxf(tm, fmaxf(acc[mi][nj][2 * half], acc[mi][nj][2 * half + 1]));
                float nm = fmaxf(m_run[slot], tm);
                float s = 0.f;
#pragma unroll
                for (int nj = 0; nj < 8; nj++)
                    s += __expf(acc[mi][nj][2 * half] - nm) +
                         __expf(acc[mi][nj][2 * half + 1] - nm);
                s_run[slot] = s_run[slot] * __expf(m_run[slot] - nm) + s;
                m_run[slot] = nm;
            }
    }

#pragma unroll
    for (int off = 1; off <= 2; off <<= 1) {
#pragma unroll
        for (int slot = 0; slot < 4; slot++) {
            float om = __shfl_xor_sync(0xffffffffu, m_run[slot], off);
            float os = __shfl_xor_sync(0xffffffffu, s_run[slot], off);
            float nm = fmaxf(m_run[slot], om);
            s_run[slot] = s_run[slot] * __expf(m_run[slot] - nm) + os * __expf(om - nm);
            m_run[slot] = nm;
        }
    }
    __syncthreads();
    if ((lane & 3) == 0) {
#pragma unroll
        for (int mi = 0; mi < 2; mi++)
#pragma unroll
            for (int half = 0; half < 2; half++) {
                int slot = mi * 2 + half;
                int row = wm + mi * 16 + half * 8 + (lane >> 2);
                sred[wid & 1][row] = make_float2(m_run[slot], s_run[slot]);
            }
    }
    __syncthreads();
    if (tid < 128) {
        float2 A0 = sred[0][tid], B0 = sred[1][tid];
        float nm = fmaxf(A0.x, B0.x);
        float s = A0.y * __expf(A0.x - nm) + B0.y * __expf(B0.x - nm);
        g_stp[(qs * NH + nh) * Ss + k0 + tid] = make_float2(nm, s);
    }
}

// ---------------- combine partial stats ----------------
__global__ void k_stcomb() {
    int i = blockIdx.x * 256 + threadIdx.x;   // i in [0, NH*Ss)
    float m = -1e30f;
#pragma unroll
    for (int qs = 0; qs < QSPLIT; qs++)
        m = fmaxf(m, g_stp[qs * NH * Ss + i].x);
    float s = 0.f;
#pragma unroll
    for (int qs = 0; qs < QSPLIT; qs++) {
        float2 p = g_stp[qs * NH * Ss + i];
        s += p.y * __expf(p.x - m);
    }
    g_st[i] = make_float2(m, 1.0f / s);
}

// ---------------- pass 2: flash attn, k split ----------------
// grid (32 qtiles, NH, KSPLIT), block 256 = 8 warps, warp tile 16q x 64
__global__ __launch_bounds__(256) void k_flash() {
    int nh = blockIdx.y;
    int ks = blockIdx.z;
    int q0 = blockIdx.x * 128;
    const __half* Qp = g_Qh + (size_t)nh * Ss * Dh;
    const __half* Kp = g_Kh + (size_t)nh * Ss * Dh;
    const __half* Vp = g_Vh + (size_t)nh * Ss * Dh;
    const float2* St = g_st + nh * Ss;
    constexpr int NITER = Ss / 64 / KSPLIT;   // 16
    int kbase = ks * (Ss / KSPLIT);

    __shared__ __half Qs[128][72];
    __shared__ __half Ks[2][64][72];
    __shared__ __half Vs[2][64][72];

    int tid = threadIdx.x, lane = tid & 31, wid = tid >> 5;
    int wm = wid * 16;

#pragma unroll
    for (int i = 0; i < 4; i++) {
        int idx = tid + i * 256;
        int r = idx >> 3, c8 = idx & 7;
        *(float4*)&Qs[r][c8 * 8] = *(const float4*)(Qp + (size_t)(q0 + r) * Dh + c8 * 8);
    }
#pragma unroll
    for (int i = 0; i < 2; i++) {
        int idx = tid + i * 256;
        int r = idx >> 3, c8 = idx & 7;
        cpa16(smem_u32(&Ks[0][r][c8 * 8]), Kp + (size_t)(kbase + r) * Dh + c8 * 8);
        cpa16(smem_u32(&Vs[0][r][c8 * 8]), Vp + (size_t)(kbase + r) * Dh + c8 * 8);
    }
    cpa_commit();
    __syncthreads();

    unsigned aq[4][4];
#pragma unroll
    for (int t = 0; t < 4; t++)
        ldmx4(aq[t], smem_u32(&Qs[wm + (lane & 15)][t * 16 + (lane >> 4) * 8]));

    float accO[8][4] = {};

    for (int c = 0; c < NITER; c++) {
        __syncthreads();
        if (c + 1 < NITER) {
            int kb1 = kbase + (c + 1) * 64;
            int bufn = (c + 1) & 1;
#pragma unroll
            for (int i = 0; i < 2; i++) {
                int idx = tid + i * 256;
                int r = idx >> 3, c8 = idx & 7;
                cpa16(smem_u32(&Ks[bufn][r][c8 * 8]), Kp + (size_t)(kb1 + r) * Dh + c8 * 8);
                cpa16(smem_u32(&Vs[bufn][r][c8 * 8]), Vp + (size_t)(kb1 + r) * Dh + c8 * 8);
            }
            cpa_commit();
            cpa_wait<1>();
        } else {
            cpa_wait<0>();
        }
        __syncthreads();
        int buf = c & 1;
        int kb = kbase + c * 64;

        float accS[8][4] = {};
#pragma unroll
        for (int t = 0; t < 4; t++) {
            unsigned b[8][2];
#pragma unroll
            for (int p = 0; p < 4; p++) {
                unsigned r4[4];
                ldmx4(r4, smem_u32(&Ks[buf][p * 16 + (lane & 7) + (lane >> 4) * 8]
                                         [t * 16 + ((lane >> 3) & 1) * 8]));
                b[2 * p][0] = r4[0]; b[2 * p][1] = r4[1];
                b[2 * p + 1][0] = r4[2]; b[2 * p + 1][1] = r4[3];
            }
#pragma unroll
            for (int nj = 0; nj < 8; nj++)
                mma16816(accS[nj], aq[t], b[nj]);
        }

        unsigned ap[4][4];
#pragma unroll
        for (int nj = 0; nj < 8; nj++) {
            int col = kb + nj * 8 + 2 * (lane & 3);
            float2 st0 = St[col];
            float2 st1 = St[col + 1];
            float p0 = __expf(accS[nj][0] - st0.x) * st0.y;
            float p1 = __expf(accS[nj][1] - st1.x) * st1.y;
            float p2 = __expf(accS[nj][2] - st0.x) * st0.y;
            float p3 = __expf(accS[nj][3] - st1.x) * st1.y;
            int t = nj >> 1, w2 = (nj & 1) * 2;
            __half2 h0 = __floats2half2_rn(p0, p1);
            __half2 h1 = __floats2half2_rn(p2, p3);
            ap[t][w2]     = *(unsigned*)&h0;
            ap[t][w2 + 1] = *(unsigned*)&h1;
        }

#pragma unroll
        for (int t = 0; t < 4; t++) {
            unsigned bv[8][2];
#pragma unroll
            for (int p = 0; p < 4; p++) {
                unsigned r4[4];
                ldmx4t(r4, smem_u32(&Vs[buf][t * 16 + (lane & 7) + ((lane >> 3) & 1) * 8]
                                          [p * 16 + (lane >> 4) * 8]));
                bv[2 * p][0] = r4[0]; bv[2 * p][1] = r4[1];
                bv[2 * p + 1][0] = r4[2]; bv[2 * p + 1][1] = r4[3];
            }
#pragma unroll
            for (int dj = 0; dj < 8; dj++)
                mma16816(accO[dj], ap[t], bv[dj]);
        }
    }

    // partial O: g_po[(ks*NH + nh)*Ss + q][d]
    float* Po = g_po + ((size_t)(ks * NH + nh) * Ss) * Dh;
#pragma unroll
    for (int dj = 0; dj < 8; dj++) {
        int q = q0 + wm + (lane >> 2);
        int col = dj * 8 + 2 * (lane & 3);
        *(float2*)(Po + (size_t)q * Dh + col) = make_float2(accO[dj][0], accO[dj][1]);
        *(float2*)(Po + (size_t)(q + 8) * Dh + col) = make_float2(accO[dj][2], accO[dj][3]);
    }
}

// ---------------- combine partial O -> g_attn ----------------
__global__ void k_ocomb() {
    int i = blockIdx.x * 256 + threadIdx.x;   // over NH*Ss*Dh
    int d = i & 63;
    int q = (i >> 6) & 4095;
    int nh = i >> 18;
    int n = nh >> 2, h = nh & 3;
    float s = 0.f;
#pragma unroll
    for (int ks = 0; ks < KSPLIT; ks++)
        s += g_po[((size_t)(ks * NH + nh) * Ss + q) * Dh + d];
    g_attn[((size_t)n * Ss + q) * Cc + h * Dh + d] = s;
}

// ---------------- MLP GEMMs, fp16 mma ----------------
// MODE 0: g_h1h = half(gelu(uh @ W1h + b1));  MODE 1: g_o = h1h @ W2h + b2 + g_attn
// grid (64, 4), block 256 = 8 warps (4m x 2n)
template <int MODE>
__global__ __launch_bounds__(256) void k_mlp(const float* __restrict__ bias) {
    int m0 = blockIdx.x * 128;
    int n0 = blockIdx.y * 64;
    const __half* A = (MODE == 0) ? g_uh : g_h1h;
    const __half* W = (MODE == 0) ? g_W1h : g_W2h;

    __shared__ __half As[128][88];
    __shared__ __half Bs[64][88];
    int tid = threadIdx.x, lane = tid & 31, wid = tid >> 5;
    int wm = (wid >> 1) * 32;
    int wn = (wid & 1) * 32;
    float acc[2][4][4] = {};

    for (int kb = 0; kb < Cc; kb += 64) {
#pragma unroll
        for (int i = 0; i < 4; i++) {
            int idx = tid + i * 256;
            int r = idx >> 3, c8 = idx & 7;
            *(float4*)&As[r][c8 * 8] = *(const float4*)(A + (size_t)(m0 + r) * Cc + kb + c8 * 8);
        }
#pragma unroll
        for (int i = 0; i < 2; i++) {
            int idx = tid + i * 256;
            int r = idx >> 3, c8 = idx & 7;
            *(float4*)&Bs[r][c8 * 8] = *(const float4*)(W + (size_t)(kb + r) * Cc + n0 + c8 * 8);
        }
        __syncthreads();
#pragma unroll
        for (int kk = 0; kk < 64; kk += 16) {
            unsigned a[2][4], b[4][2];
#pragma unroll
            for (int mi = 0; mi < 2; mi++)
                ldmx4(a[mi], smem_u32(&As[wm + mi * 16 + (lane & 15)][kk + (lane >> 4) * 8]));
#pragma unroll
            for (int p = 0; p < 2; p++) {
                unsigned r4[4];
                ldmx4t(r4, smem_u32(&Bs[kk + (lane & 7) + ((lane >> 3) & 1) * 8]
                                       [wn + p * 16 + (lane >> 4) * 8]));
                b[2 * p][0] = r4[0]; b[2 * p][1] = r4[1];
                b[2 * p + 1][0] = r4[2]; b[2 * p + 1][1] = r4[3];
            }
#pragma unroll
            for (int mi = 0; mi < 2; mi++)
#pragma unroll
                for (int nj = 0; nj < 4; nj++)
                    mma16816(acc[mi][nj], a[mi], b[nj]);
        }
        __syncthreads();
    }
#pragma unroll
    for (int mi = 0; mi < 2; mi++) {
#pragma unroll
        for (int half = 0; half < 2; half++) {
            int row = m0 + wm + mi * 16 + half * 8 + (lane >> 2);
#pragma unroll
            for (int nj = 0; nj < 4; nj++) {
                int col = n0 + wn + nj * 8 + 2 * (lane & 3);
                float v0 = acc[mi][nj][2 * half]     + bias[col];
                float v1 = acc[mi][nj][2 * half + 1] + bias[col + 1];
                if (MODE == 0) {
                    v0 = 0.5f * v0 * (1.0f + erff(v0 * 0.70710678118654752f));
                    v1 = 0.5f * v1 * (1.0f + erff(v1 * 0.70710678118654752f));
                    *(__half2*)(g_h1h + (size_t)row * Cc + col) = __floats2half2_rn(v0, v1);
                } else {
                    v0 += g_attn[(size_t)row * Cc + col];
                    v1 += g_attn[(size_t)row * Cc + col + 1];
                    *(float2*)(g_o + (size_t)row * Cc + col) = make_float2(v0, v1);
                }
            }
        }
    }
}

// ---------------- launch ----------------
extern "C" void kernel_launch(void* const* d_in, const int* in_sizes, int n_in,
                              void* d_out, int out_size) {
    const float* x     = (const float*)d_in[0];
    const float* ln1_w = (const float*)d_in[1];
    const float* ln1_b = (const float*)d_in[2];
    const float* WQ    = (const float*)d_in[3];
    const float* WK    = (const float*)d_in[4];
    const float* WV    = (const float*)d_in[5];
    const float* ln2_w = (const float*)d_in[6];
    const float* ln2_b = (const float*)d_in[7];
    const float* W1    = (const float*)d_in[8];
    const float* b1    = (const float*)d_in[9];
    const float* W2    = (const float*)d_in[10];
    const float* b2    = (const float*)d_in[11];
    float* out = (float*)d_out;

    dim3 tb(32, 8);
    k_transpose_in<<<dim3(Ss / 32, Cc / 32, Nb), tb>>>(x);
    k_cvtw<<<Cc * Cc / 256, 256>>>(W1, W2);
    k_ln<0><<<Nb * Ss, 256>>>(ln1_w, ln1_b);

    k_qkv<<<dim3(Ss / 128, 12, Nb), 256>>>(WQ, WK, WV);

    k_stats<<<dim3(Ss / 128, NH, QSPLIT), 256>>>();
    k_stcomb<<<NH * Ss / 256, 256>>>();
    k_flash<<<dim3(Ss / 128, NH, KSPLIT), 256>>>();
    k_ocomb<<<NH * Ss * Dh / 256, 256>>>();

    k_ln<1><<<Nb * Ss, 256>>>(ln2_w, ln2_b);
    k_mlp<0><<<dim3(64, 4), 256>>>(b1);
    k_mlp<1><<<dim3(64, 4), 256>>>(b2);

    k_transpose_out<<<dim3(Ss / 32, Cc / 32, Nb), tb>>>(out);
}

// round 6
// speedup vs baseline: 5.6862x; 1.0266x over previous
#include <cuda_runtime.h>
#include <cuda_fp16.h>
#include <cstdint>
#include <stdint.h>
#include <math.h>

// ---------------- problem constants ----------------
constexpr int Nb = 2;
constexpr int Cc = 256;
constexpr int Ss = 4096;
constexpr int Hh = 4;
constexpr int Dh = 64;
constexpr int NH = Nb * Hh;
constexpr float EPSV = 1e-5f;
constexpr float SCALE = 1.0f / 64.0f;
constexpr int QSPLIT = 4;
constexpr int KSPLIT = 4;

// ---------------- device scratch ----------------
__device__ float  g_r    [Nb * Ss * Cc];
__device__ __half g_normh[Nb * Ss * Cc];
__device__ __half g_Qh   [NH * Ss * Dh];   // pre-scaled by SCALE
__device__ __half g_Kh   [NH * Ss * Dh];
__device__ __half g_Vh   [NH * Ss * Dh];
__device__ float2 g_stp  [QSPLIT * NH * Ss];
__device__ float2 g_st   [NH * Ss];
__device__ float  g_po   [KSPLIT * NH * Ss * Dh];
__device__ float  g_attn [Nb * Ss * Cc];
__device__ __half g_uh   [Nb * Ss * Cc];
__device__ __half g_h1h  [Nb * Ss * Cc];
__device__ __half g_W1h  [Cc * Cc];
__device__ __half g_W2h  [Cc * Cc];
__device__ float  g_o    [Nb * Ss * Cc];

// ---------------- helpers ----------------
__device__ __forceinline__ unsigned smem_u32(const void* p) {
    return (unsigned)__cvta_generic_to_shared(p);
}
__device__ __forceinline__ void ldmx4(unsigned* r, unsigned a) {
    asm volatile("ldmatrix.sync.aligned.m8n8.x4.shared.b16 {%0,%1,%2,%3},[%4];"
                 : "=r"(r[0]), "=r"(r[1]), "=r"(r[2]), "=r"(r[3]) : "r"(a));
}
__device__ __forceinline__ void ldmx4t(unsigned* r, unsigned a) {
    asm volatile("ldmatrix.sync.aligned.m8n8.x4.trans.shared.b16 {%0,%1,%2,%3},[%4];"
                 : "=r"(r[0]), "=r"(r[1]), "=r"(r[2]), "=r"(r[3]) : "r"(a));
}
__device__ __forceinline__ void mma16816(float* c, const unsigned* a, const unsigned* b) {
    asm volatile(
        "mma.sync.aligned.m16n8k16.row.col.f32.f16.f16.f32 "
        "{%0,%1,%2,%3},{%4,%5,%6,%7},{%8,%9},{%0,%1,%2,%3};"
        : "+f"(c[0]), "+f"(c[1]), "+f"(c[2]), "+f"(c[3])
        : "r"(a[0]), "r"(a[1]), "r"(a[2]), "r"(a[3]), "r"(b[0]), "r"(b[1]));
}
__device__ __forceinline__ void cpa16(unsigned dst, const void* src) {
    asm volatile("cp.async.ca.shared.global [%0], [%1], 16;" :: "r"(dst), "l"(src));
}
__device__ __forceinline__ void cpa_commit() {
    asm volatile("cp.async.commit_group;");
}
template <int N>
__device__ __forceinline__ void cpa_wait() {
    asm volatile("cp.async.wait_group %0;" :: "n"(N));
}

// ---------------- fused: transpose x[n,c,s] -> r[n,s,c] + LN1 -> normh ----------------
// grid (Ss/32, Nb), block (32, 8)
__global__ void k_tin_ln(const float* __restrict__ x,
                         const float* __restrict__ w, const float* __restrict__ b) {
    __shared__ float t[256][33];
    int n = blockIdx.y, s0 = blockIdx.x * 32;
    int tx = threadIdx.x, ty = threadIdx.y;
#pragma unroll
    for (int i = 0; i < 32; i++)
        t[ty + 8 * i][tx] = x[((size_t)(n * Cc + ty + 8 * i)) * Ss + s0 + tx];
    __syncthreads();
    int lane = tx;
#pragma unroll
    for (int j = 0; j < 4; j++) {
        int s = ty * 4 + j;
        float vals[8];
        float s1 = 0.f, s2 = 0.f;
#pragma unroll
        for (int u = 0; u < 8; u++) {
            float v = t[lane + 32 * u][s];
            vals[u] = v; s1 += v; s2 += v * v;
        }
#pragma unroll
        for (int o = 16; o; o >>= 1) {
            s1 += __shfl_xor_sync(0xffffffffu, s1, o);
            s2 += __shfl_xor_sync(0xffffffffu, s2, o);
        }
        float mean = s1 * (1.0f / Cc);
        float rstd = rsqrtf(s2 * (1.0f / Cc) - mean * mean + EPSV);
        size_t rowo = ((size_t)n * Ss + s0 + s) * Cc;
#pragma unroll
        for (int u = 0; u < 8; u++) {
            int c = lane + 32 * u;
            g_r[rowo + c] = vals[u];
            g_normh[rowo + c] = __float2half((vals[u] - mean) * rstd * w[c] + b[c]);
        }
    }
}

// ---------------- transpose out ----------------
__global__ void k_transpose_out(float* __restrict__ out) {
    __shared__ float t[32][33];
    int n = blockIdx.z;
    int s0 = blockIdx.x * 32, c0 = blockIdx.y * 32;
    int tx = threadIdx.x, ty = threadIdx.y;
#pragma unroll
    for (int i = 0; i < 4; i++)
        t[ty + 8 * i][tx] = g_o[((size_t)(n * Ss + s0 + ty + 8 * i)) * Cc + c0 + tx];
    __syncthreads();
#pragma unroll
    for (int i = 0; i < 4; i++)
        out[((size_t)(n * Cc + c0 + ty + 8 * i)) * Ss + s0 + tx] = t[tx][ty + 8 * i];
}

// ---------------- weight fp32 -> fp16 ----------------
__global__ void k_cvtw(const float* __restrict__ W1, const float* __restrict__ W2) {
    int i = blockIdx.x * 256 + threadIdx.x;
    g_W1h[i] = __float2half(W1[i]);
    g_W2h[i] = __float2half(W2[i]);
}

// ---------------- fused: O-combine + residual + LN2 -> g_attn, g_uh ----------------
__global__ void k_oln(const float* __restrict__ w, const float* __restrict__ b) {
    int row = blockIdx.x;              // n*Ss + q
    int t = threadIdx.x;               // c
    int n = row >> 12, q = row & 4095;
    int h = t >> 6, d = t & 63;
    int nh = n * 4 + h;
    float val = 0.f;
#pragma unroll
    for (int ks = 0; ks < KSPLIT; ks++)
        val += g_po[((size_t)(ks * NH + nh) * Ss + q) * Dh + d];
    size_t idx = (size_t)row * Cc + t;
    g_attn[idx] = val;
    float v = val + g_r[idx];

    float s1 = v, s2 = v * v;
#pragma unroll
    for (int o = 16; o; o >>= 1) {
        s1 += __shfl_xor_sync(0xffffffffu, s1, o);
        s2 += __shfl_xor_sync(0xffffffffu, s2, o);
    }
    __shared__ float sm1[8], sm2[8];
    __shared__ float mb, rb;
    int w8 = t >> 5, lane = t & 31;
    if (!lane) { sm1[w8] = s1; sm2[w8] = s2; }
    __syncthreads();
    if (t == 0) {
        float a = 0.f, qq = 0.f;
#pragma unroll
        for (int i = 0; i < 8; i++) { a += sm1[i]; qq += sm2[i]; }
        float mean = a * (1.0f / Cc);
        mb = mean;
        rb = rsqrtf(qq * (1.0f / Cc) - mean * mean + EPSV);
    }
    __syncthreads();
    g_uh[idx] = __float2half((v - mb) * rb * w[t] + b[t]);
}

// ---------------- QKV projection, fp16 mma (Q pre-scaled) ----------------
__global__ __launch_bounds__(256) void k_qkv(const float* __restrict__ WQ,
                                             const float* __restrict__ WK,
                                             const float* __restrict__ WV) {
    int which = blockIdx.y >> 2;
    int h = blockIdx.y & 3;
    int n = blockIdx.z;
    int m0 = blockIdx.x * 128;
    const float* W = (which == 0 ? WQ : which == 1 ? WK : WV) + h * Cc * Dh;
    __half* Out = (which == 0 ? g_Qh : which == 1 ? g_Kh : g_Vh) + (size_t)(n * 4 + h) * Ss * Dh;
    const __half* A = g_normh + (size_t)n * Ss * Cc;
    float oscale = (which == 0) ? SCALE : 1.0f;

    __shared__ __half As[128][88];
    __shared__ __half Bs[64][88];
    int tid = threadIdx.x, lane = tid & 31, wid = tid >> 5;
    int wm = (wid >> 1) * 32;
    int wn = (wid & 1) * 32;
    float acc[2][4][4] = {};

    for (int kb = 0; kb < Cc; kb += 64) {
#pragma unroll
        for (int i = 0; i < 4; i++) {
            int idx = tid + i * 256;
            int r = idx >> 3, c8 = idx & 7;
            *(float4*)&As[r][c8 * 8] = *(const float4*)(A + (size_t)(m0 + r) * Cc + kb + c8 * 8);
        }
#pragma unroll
        for (int i = 0; i < 4; i++) {
            int idx = tid + i * 256;
            int r = idx >> 4, c4 = idx & 15;
            float4 v = *(const float4*)(W + (size_t)(kb + r) * Dh + c4 * 4);
            __half2* d = (__half2*)&Bs[r][c4 * 4];
            d[0] = __floats2half2_rn(v.x, v.y);
            d[1] = __floats2half2_rn(v.z, v.w);
        }
        __syncthreads();
#pragma unroll
        for (int kk = 0; kk < 64; kk += 16) {
            unsigned a[2][4], b[4][2];
#pragma unroll
            for (int mi = 0; mi < 2; mi++)
                ldmx4(a[mi], smem_u32(&As[wm + mi * 16 + (lane & 15)][kk + (lane >> 4) * 8]));
#pragma unroll
            for (int p = 0; p < 2; p++) {
                unsigned r4[4];
                ldmx4t(r4, smem_u32(&Bs[kk + (lane & 7) + ((lane >> 3) & 1) * 8]
                                       [wn + p * 16 + (lane >> 4) * 8]));
                b[2 * p][0] = r4[0]; b[2 * p][1] = r4[1];
                b[2 * p + 1][0] = r4[2]; b[2 * p + 1][1] = r4[3];
            }
#pragma unroll
            for (int mi = 0; mi < 2; mi++)
#pragma unroll
                for (int nj = 0; nj < 4; nj++)
                    mma16816(acc[mi][nj], a[mi], b[nj]);
        }
        __syncthreads();
    }
#pragma unroll
    for (int mi = 0; mi < 2; mi++) {
        int r = m0 + wm + mi * 16 + (lane >> 2);
#pragma unroll
        for (int nj = 0; nj < 4; nj++) {
            int c = wn + nj * 8 + 2 * (lane & 3);
            *(__half2*)(Out + (size_t)r * Dh + c) =
                __floats2half2_rn(acc[mi][nj][0] * oscale, acc[mi][nj][1] * oscale);
            *(__half2*)(Out + (size_t)(r + 8) * Dh + c) =
                __floats2half2_rn(acc[mi][nj][2] * oscale, acc[mi][nj][3] * oscale);
        }
    }
}

// ---------------- pass 1: per-k partial softmax stats (q split) ----------------
__global__ __launch_bounds__(256) void k_stats() {
    int nh = blockIdx.y;
    int qs = blockIdx.z;
    int k0 = blockIdx.x * 128;
    const __half* Kp = g_Kh + (size_t)nh * Ss * Dh;
    const __half* Qp = g_Qh + (size_t)nh * Ss * Dh;
    constexpr int NITER = Ss / 128 / QSPLIT;
    int qbase = qs * (Ss / QSPLIT);

    __shared__ __half As[128][72];
    __shared__ __half Bs[2][128][72];
    __shared__ float2 sred[2][128];

    int tid = threadIdx.x, lane = tid & 31, wid = tid >> 5;
    int wm = (wid >> 1) * 32;
    int wn = (wid & 1) * 64;

#pragma unroll
    for (int i = 0; i < 4; i++) {
        int idx = tid + i * 256;
        int r = idx >> 3, c8 = idx & 7;
        *(float4*)&As[r][c8 * 8] = *(const float4*)(Kp + (size_t)(k0 + r) * Dh + c8 * 8);
    }
#pragma unroll
    for (int i = 0; i < 4; i++) {
        int idx = tid + i * 256;
        int r = idx >> 3, c8 = idx & 7;
        cpa16(smem_u32(&Bs[0][r][c8 * 8]), Qp + (size_t)(qbase + r) * Dh + c8 * 8);
    }
    cpa_commit();
    __syncthreads();

    unsigned a[2][4][4];
#pragma unroll
    for (int mi = 0; mi < 2; mi++)
#pragma unroll
        for (int t = 0; t < 4; t++)
            ldmx4(a[mi][t], smem_u32(&As[wm + mi * 16 + (lane & 15)][t * 16 + (lane >> 4) * 8]));

    float m_run[4] = {-1e30f, -1e30f, -1e30f, -1e30f};
    float s_run[4] = {0.f, 0.f, 0.f, 0.f};

    for (int c = 0; c < NITER; c++) {
        __syncthreads();
        if (c + 1 < NITER) {
            int q1 = qbase + (c + 1) * 128;
            int bufn = (c + 1) & 1;
#pragma unroll
            for (int i = 0; i < 4; i++) {
                int idx = tid + i * 256;
                int r = idx >> 3, c8 = idx & 7;
                cpa16(smem_u32(&Bs[bufn][r][c8 * 8]), Qp + (size_t)(q1 + r) * Dh + c8 * 8);
            }
            cpa_commit();
            cpa_wait<1>();
        } else {
            cpa_wait<0>();
        }
        __syncthreads();
        int buf = c & 1;

        float acc[2][8][4] = {};
#pragma unroll
        for (int t = 0; t < 4; t++) {
            unsigned b[8][2];
#pragma unroll
            for (int p = 0; p < 4; p++) {
                unsigned r4[4];
                ldmx4(r4, smem_u32(&Bs[buf][wn + p * 16 + (lane & 7) + (lane >> 4) * 8]
                                         [t * 16 + ((lane >> 3) & 1) * 8]));
                b[2 * p][0] = r4[0]; b[2 * p][1] = r4[1];
                b[2 * p + 1][0] = r4[2]; b[2 * p + 1][1] = r4[3];
            }
#pragma unroll
            for (int mi = 0; mi < 2; mi++)
#pragma unroll
                for (int nj = 0; nj < 8; nj++)
                    mma16816(acc[mi][nj], a[mi][t], b[nj]);
        }
#pragma unroll
        for (int mi = 0; mi < 2; mi++)
#pragma unroll
            for (int half = 0; half < 2; half++) {
                int slot = mi * 2 + half;
                float tm = -1e30f;
#pragma unroll
                for (int nj = 0; nj < 8; nj++)
                    tm = fmaxf(tm, fmaxf(acc[mi][nj][2 * half], acc[mi][nj][2 * half + 1]));
                float nm = fmaxf(m_run[slot], tm);
                float s = 0.f;
#pragma unroll
                for (int nj = 0; nj < 8; nj++)
                    s += __expf(acc[mi][nj][2 * half] - nm) +
                         __expf(acc[mi][nj][2 * half + 1] - nm);
                s_run[slot] = s_run[slot] * __expf(m_run[slot] - nm) + s;
                m_run[slot] = nm;
            }
    }

#pragma unroll
    for (int off = 1; off <= 2; off <<= 1) {
#pragma unroll
        for (int slot = 0; slot < 4; slot++) {
            float om = __shfl_xor_sync(0xffffffffu, m_run[slot], off);
            float os = __shfl_xor_sync(0xffffffffu, s_run[slot], off);
            float nm = fmaxf(m_run[slot], om);
            s_run[slot] = s_run[slot] * __expf(m_run[slot] - nm) + os * __expf(om - nm);
            m_run[slot] = nm;
        }
    }
    __syncthreads();
    if ((lane & 3) == 0) {
#pragma unroll
        for (int mi = 0; mi < 2; mi++)
#pragma unroll
            for (int half = 0; half < 2; half++) {
                int slot = mi * 2 + half;
                int row = wm + mi * 16 + half * 8 + (lane >> 2);
                sred[wid & 1][row] = make_float2(m_run[slot], s_run[slot]);
            }
    }
    __syncthreads();
    if (tid < 128) {
        float2 A0 = sred[0][tid], B0 = sred[1][tid];
        float nm = fmaxf(A0.x, B0.x);
        float s = A0.y * __expf(A0.x - nm) + B0.y * __expf(B0.x - nm);
        g_stp[(qs * NH + nh) * Ss + k0 + tid] = make_float2(nm, s);
    }
}

// ---------------- combine partial stats ----------------
__global__ void k_stcomb() {
    int i = blockIdx.x * 256 + threadIdx.x;
    float m = -1e30f;
#pragma unroll
    for (int qs = 0; qs < QSPLIT; qs++)
        m = fmaxf(m, g_stp[qs * NH * Ss + i].x);
    float s = 0.f;
#pragma unroll
    for (int qs = 0; qs < QSPLIT; qs++) {
        float2 p = g_stp[qs * NH * Ss + i];
        s += p.y * __expf(p.x - m);
    }
    g_st[i] = make_float2(m, 1.0f / s);
}

// ---------------- pass 2: flash attn, k split, 32-k chunks, 2 blocks/SM ----------------
__global__ __launch_bounds__(256, 2) void k_flash() {
    int nh = blockIdx.y;
    int ks = blockIdx.z;
    int q0 = blockIdx.x * 128;
    const __half* Qp = g_Qh + (size_t)nh * Ss * Dh;
    const __half* Kp = g_Kh + (size_t)nh * Ss * Dh;
    const __half* Vp = g_Vh + (size_t)nh * Ss * Dh;
    const float2* St = g_st + nh * Ss;
    constexpr int NITER = Ss / 32 / KSPLIT;   // 32
    int kbase = ks * (Ss / KSPLIT);

    __shared__ __half Qs[128][72];
    __shared__ __half Ks[2][32][72];
    __shared__ __half Vs[2][32][72];

    int tid = threadIdx.x, lane = tid & 31, wid = tid >> 5;
    int wm = wid * 16;

#pragma unroll
    for (int i = 0; i < 4; i++) {
        int idx = tid + i * 256;
        int r = idx >> 3, c8 = idx & 7;
        *(float4*)&Qs[r][c8 * 8] = *(const float4*)(Qp + (size_t)(q0 + r) * Dh + c8 * 8);
    }
    {
        int r = tid >> 3, c8 = tid & 7;
        cpa16(smem_u32(&Ks[0][r][c8 * 8]), Kp + (size_t)(kbase + r) * Dh + c8 * 8);
        cpa16(smem_u32(&Vs[0][r][c8 * 8]), Vp + (size_t)(kbase + r) * Dh + c8 * 8);
    }
    cpa_commit();
    __syncthreads();

    unsigned aq[4][4];
#pragma unroll
    for (int t = 0; t < 4; t++)
        ldmx4(aq[t], smem_u32(&Qs[wm + (lane & 15)][t * 16 + (lane >> 4) * 8]));

    float accO[8][4] = {};

    for (int c = 0; c < NITER; c++) {
        __syncthreads();
        if (c + 1 < NITER) {
            int kb1 = kbase + (c + 1) * 32;
            int bufn = (c + 1) & 1;
            int r = tid >> 3, c8 = tid & 7;
            cpa16(smem_u32(&Ks[bufn][r][c8 * 8]), Kp + (size_t)(kb1 + r) * Dh + c8 * 8);
            cpa16(smem_u32(&Vs[bufn][r][c8 * 8]), Vp + (size_t)(kb1 + r) * Dh + c8 * 8);
            cpa_commit();
            cpa_wait<1>();
        } else {
            cpa_wait<0>();
        }
        __syncthreads();
        int buf = c & 1;
        int kb = kbase + c * 32;

        // S = Q K^T  [16q x 32k] per warp
        float accS[4][4] = {};
#pragma unroll
        for (int t = 0; t < 4; t++) {
            unsigned b[4][2];
#pragma unroll
            for (int p = 0; p < 2; p++) {
                unsigned r4[4];
                ldmx4(r4, smem_u32(&Ks[buf][p * 16 + (lane & 7) + (lane >> 4) * 8]
                                         [t * 16 + ((lane >> 3) & 1) * 8]));
                b[2 * p][0] = r4[0]; b[2 * p][1] = r4[1];
                b[2 * p + 1][0] = r4[2]; b[2 * p + 1][1] = r4[3];
            }
#pragma unroll
            for (int nj = 0; nj < 4; nj++)
                mma16816(accS[nj], aq[t], b[nj]);
        }

        // P = exp(S - m_k)*inv_k packed into A fragments [16q x 32k]
        unsigned ap[2][4];
#pragma unroll
        for (int nj = 0; nj < 4; nj++) {
            int col = kb + nj * 8 + 2 * (lane & 3);
            float2 st0 = St[col];
            float2 st1 = St[col + 1];
            float p0 = __expf(accS[nj][0] - st0.x) * st0.y;
            float p1 = __expf(accS[nj][1] - st1.x) * st1.y;
            float p2 = __expf(accS[nj][2] - st0.x) * st0.y;
            float p3 = __expf(accS[nj][3] - st1.x) * st1.y;
            int t = nj >> 1, w2 = (nj & 1) * 2;
            __half2 h0 = __floats2half2_rn(p0, p1);
            __half2 h1 = __floats2half2_rn(p2, p3);
            ap[t][w2]     = *(unsigned*)&h0;
            ap[t][w2 + 1] = *(unsigned*)&h1;
        }

        // O += P V   [16q x 64d] per warp
#pragma unroll
        for (int t = 0; t < 2; t++) {
            unsigned bv[8][2];
#pragma unroll
            for (int p = 0; p < 4; p++) {
                unsigned r4[4];
                ldmx4t(r4, smem_u32(&Vs[buf][t * 16 + (lane & 7) + ((lane >> 3) & 1) * 8]
                                          [p * 16 + (lane >> 4) * 8]));
                bv[2 * p][0] = r4[0]; bv[2 * p][1] = r4[1];
                bv[2 * p + 1][0] = r4[2]; bv[2 * p + 1][1] = r4[3];
            }
#pragma unroll
            for (int dj = 0; dj < 8; dj++)
                mma16816(accO[dj], ap[t], bv[dj]);
        }
    }

    float* Po = g_po + ((size_t)(ks * NH + nh) * Ss) * Dh;
#pragma unroll
    for (int dj = 0; dj < 8; dj++) {
        int q = q0 + wm + (lane >> 2);
        int col = dj * 8 + 2 * (lane & 3);
        *(float2*)(Po + (size_t)q * Dh + col) = make_float2(accO[dj][0], accO[dj][1]);
        *(float2*)(Po + (size_t)(q + 8) * Dh + col) = make_float2(accO[dj][2], accO[dj][3]);
    }
}

// ---------------- MLP GEMMs, fp16 mma ----------------
template <int MODE>
__global__ __launch_bounds__(256) void k_mlp(const float* __restrict__ bias) {
    int m0 = blockIdx.x * 128;
    int n0 = blockIdx.y * 64;
    const __half* A = (MODE == 0) ? g_uh : g_h1h;
    const __half* W = (MODE == 0) ? g_W1h : g_W2h;

    __shared__ __half As[128][88];
    __shared__ __half Bs[64][88];
    int tid = threadIdx.x, lane = tid & 31, wid = tid >> 5;
    int wm = (wid >> 1) * 32;
    int wn = (wid & 1) * 32;
    float acc[2][4][4] = {};

    for (int kb = 0; kb < Cc; kb += 64) {
#pragma unroll
        for (int i = 0; i < 4; i++) {
            int idx = tid + i * 256;
            int r = idx >> 3, c8 = idx & 7;
            *(float4*)&As[r][c8 * 8] = *(const float4*)(A + (size_t)(m0 + r) * Cc + kb + c8 * 8);
        }
#pragma unroll
        for (int i = 0; i < 2; i++) {
            int idx = tid + i * 256;
            int r = idx >> 3, c8 = idx & 7;
            *(float4*)&Bs[r][c8 * 8] = *(const float4*)(W + (size_t)(kb + r) * Cc + n0 + c8 * 8);
        }
        __syncthreads();
#pragma unroll
        for (int kk = 0; kk < 64; kk += 16) {
            unsigned a[2][4], b[4][2];
#pragma unroll
            for (int mi = 0; mi < 2; mi++)
                ldmx4(a[mi], smem_u32(&As[wm + mi * 16 + (lane & 15)][kk + (lane >> 4) * 8]));
#pragma unroll
            for (int p = 0; p < 2; p++) {
                unsigned r4[4];
                ldmx4t(r4, smem_u32(&Bs[kk + (lane & 7) + ((lane >> 3) & 1) * 8]
                                       [wn + p * 16 + (lane >> 4) * 8]));
                b[2 * p][0] = r4[0]; b[2 * p][1] = r4[1];
                b[2 * p + 1][0] = r4[2]; b[2 * p + 1][1] = r4[3];
            }
#pragma unroll
            for (int mi = 0; mi < 2; mi++)
#pragma unroll
                for (int nj = 0; nj < 4; nj++)
                    mma16816(acc[mi][nj], a[mi], b[nj]);
        }
        __syncthreads();
    }
#pragma unroll
    for (int mi = 0; mi < 2; mi++) {
#pragma unroll
        for (int half = 0; half < 2; half++) {
            int row = m0 + wm + mi * 16 + half * 8 + (lane >> 2);
#pragma unroll
            for (int nj = 0; nj < 4; nj++) {
                int col = n0 + wn + nj * 8 + 2 * (lane & 3);
                float v0 = acc[mi][nj][2 * half]     + bias[col];
                float v1 = acc[mi][nj][2 * half + 1] + bias[col + 1];
                if (MODE == 0) {
                    v0 = 0.5f * v0 * (1.0f + erff(v0 * 0.70710678118654752f));
                    v1 = 0.5f * v1 * (1.0f + erff(v1 * 0.70710678118654752f));
                    *(__half2*)(g_h1h + (size_t)row * Cc + col) = __floats2half2_rn(v0, v1);
                } else {
                    v0 += g_attn[(size_t)row * Cc + col];
                    v1 += g_attn[(size_t)row * Cc + col + 1];
                    *(float2*)(g_o + (size_t)row * Cc + col) = make_float2(v0, v1);
                }
            }
        }
    }
}

// ---------------- launch ----------------
extern "C" void kernel_launch(void* const* d_in, const int* in_sizes, int n_in,
                              void* d_out, int out_size) {
    const float* x     = (const float*)d_in[0];
    const float* ln1_w = (const float*)d_in[1];
    const float* ln1_b = (const float*)d_in[2];
    const float* WQ    = (const float*)d_in[3];
    const float* WK    = (const float*)d_in[4];
    const float* WV    = (const float*)d_in[5];
    const float* ln2_w = (const float*)d_in[6];
    const float* ln2_b = (const float*)d_in[7];
    const float* W1    = (const float*)d_in[8];
    const float* b1    = (const float*)d_in[9];
    const float* W2    = (const float*)d_in[10];
    const float* b2    = (const float*)d_in[11];
    float* out = (float*)d_out;

    k_tin_ln<<<dim3(Ss / 32, Nb), dim3(32, 8)>>>(x, ln1_w, ln1_b);
    k_cvtw<<<Cc * Cc / 256, 256>>>(W1, W2);

    k_qkv<<<dim3(Ss / 128, 12, Nb), 256>>>(WQ, WK, WV);

    k_stats<<<dim3(Ss / 128, NH, QSPLIT), 256>>>();
    k_stcomb<<<NH * Ss / 256, 256>>>();
    k_flash<<<dim3(Ss / 128, NH, KSPLIT), 256>>>();

    k_oln<<<Nb * Ss, 256>>>(ln2_w, ln2_b);
    k_mlp<0><<<dim3(64, 4), 256>>>(b1);
    k_mlp<1><<<dim3(64, 4), 256>>>(b2);

    k_transpose_out<<<dim3(Ss / 32, Cc / 32, Nb), dim3(32, 8)>>>(out);
}

// round 7
// speedup vs baseline: 6.3730x; 1.1208x over previous
#include <cuda_runtime.h>
#include <cuda_fp16.h>
#include <cstdint>
#include <stdint.h>
#include <math.h>

// ---------------- problem constants ----------------
constexpr int Nb = 2;
constexpr int Cc = 256;
constexpr int Ss = 4096;
constexpr int Hh = 4;
constexpr int Dh = 64;
constexpr int NH = Nb * Hh;
constexpr float EPSV = 1e-5f;
constexpr float SCALE = 1.0f / 64.0f;
constexpr int QSPLIT = 4;
constexpr int KSPLIT = 4;

// ---------------- device scratch ----------------
__device__ float  g_r    [Nb * Ss * Cc];
__device__ __half g_normh[Nb * Ss * Cc];
__device__ __half g_Qh   [NH * Ss * Dh];   // pre-scaled by SCALE
__device__ __half g_Kh   [NH * Ss * Dh];
__device__ __half g_Vh   [NH * Ss * Dh];
__device__ float  g_stp  [QSPLIT * NH * Ss];  // partial sumexp
__device__ float  g_sti  [NH * Ss];           // 1/sumexp
__device__ float  g_po   [KSPLIT * NH * Ss * Dh];
__device__ float  g_attn [Nb * Ss * Cc];
__device__ __half g_uh   [Nb * Ss * Cc];
__device__ __half g_h1h  [Nb * Ss * Cc];
__device__ __half g_W1h  [Cc * Cc];
__device__ __half g_W2h  [Cc * Cc];
__device__ float  g_o    [Nb * Ss * Cc];

// ---------------- helpers ----------------
__device__ __forceinline__ unsigned smem_u32(const void* p) {
    return (unsigned)__cvta_generic_to_shared(p);
}
__device__ __forceinline__ void ldmx4(unsigned* r, unsigned a) {
    asm volatile("ldmatrix.sync.aligned.m8n8.x4.shared.b16 {%0,%1,%2,%3},[%4];"
                 : "=r"(r[0]), "=r"(r[1]), "=r"(r[2]), "=r"(r[3]) : "r"(a));
}
__device__ __forceinline__ void ldmx4t(unsigned* r, unsigned a) {
    asm volatile("ldmatrix.sync.aligned.m8n8.x4.trans.shared.b16 {%0,%1,%2,%3},[%4];"
                 : "=r"(r[0]), "=r"(r[1]), "=r"(r[2]), "=r"(r[3]) : "r"(a));
}
__device__ __forceinline__ void mma16816(float* c, const unsigned* a, const unsigned* b) {
    asm volatile(
        "mma.sync.aligned.m16n8k16.row.col.f32.f16.f16.f32 "
        "{%0,%1,%2,%3},{%4,%5,%6,%7},{%8,%9},{%0,%1,%2,%3};"
        : "+f"(c[0]), "+f"(c[1]), "+f"(c[2]), "+f"(c[3])
        : "r"(a[0]), "r"(a[1]), "r"(a[2]), "r"(a[3]), "r"(b[0]), "r"(b[1]));
}
__device__ __forceinline__ void cpa16(unsigned dst, const void* src) {
    asm volatile("cp.async.ca.shared.global [%0], [%1], 16;" :: "r"(dst), "l"(src));
}
__device__ __forceinline__ void cpa_commit() {
    asm volatile("cp.async.commit_group;");
}
template <int N>
__device__ __forceinline__ void cpa_wait() {
    asm volatile("cp.async.wait_group %0;" :: "n"(N));
}

// ---------------- fused: transpose x[n,c,s] -> r[n,s,c] + LN1 -> normh ----------------
__global__ void k_tin_ln(const float* __restrict__ x,
                         const float* __restrict__ w, const float* __restrict__ b) {
    __shared__ float t[256][33];
    int n = blockIdx.y, s0 = blockIdx.x * 32;
    int tx = threadIdx.x, ty = threadIdx.y;
#pragma unroll
    for (int i = 0; i < 32; i++)
        t[ty + 8 * i][tx] = x[((size_t)(n * Cc + ty + 8 * i)) * Ss + s0 + tx];
    __syncthreads();
    int lane = tx;
#pragma unroll
    for (int j = 0; j < 4; j++) {
        int s = ty * 4 + j;
        float vals[8];
        float s1 = 0.f, s2 = 0.f;
#pragma unroll
        for (int u = 0; u < 8; u++) {
            float v = t[lane + 32 * u][s];
            vals[u] = v; s1 += v; s2 += v * v;
        }
#pragma unroll
        for (int o = 16; o; o >>= 1) {
            s1 += __shfl_xor_sync(0xffffffffu, s1, o);
            s2 += __shfl_xor_sync(0xffffffffu, s2, o);
        }
        float mean = s1 * (1.0f / Cc);
        float rstd = rsqrtf(s2 * (1.0f / Cc) - mean * mean + EPSV);
        size_t rowo = ((size_t)n * Ss + s0 + s) * Cc;
#pragma unroll
        for (int u = 0; u < 8; u++) {
            int c = lane + 32 * u;
            g_r[rowo + c] = vals[u];
            g_normh[rowo + c] = __float2half((vals[u] - mean) * rstd * w[c] + b[c]);
        }
    }
}

// ---------------- transpose out ----------------
__global__ void k_transpose_out(float* __restrict__ out) {
    __shared__ float t[32][33];
    int n = blockIdx.z;
    int s0 = blockIdx.x * 32, c0 = blockIdx.y * 32;
    int tx = threadIdx.x, ty = threadIdx.y;
#pragma unroll
    for (int i = 0; i < 4; i++)
        t[ty + 8 * i][tx] = g_o[((size_t)(n * Ss + s0 + ty + 8 * i)) * Cc + c0 + tx];
    __syncthreads();
#pragma unroll
    for (int i = 0; i < 4; i++)
        out[((size_t)(n * Cc + c0 + ty + 8 * i)) * Ss + s0 + tx] = t[tx][ty + 8 * i];
}

// ---------------- weight fp32 -> fp16 ----------------
__global__ void k_cvtw(const float* __restrict__ W1, const float* __restrict__ W2) {
    int i = blockIdx.x * 256 + threadIdx.x;
    g_W1h[i] = __float2half(W1[i]);
    g_W2h[i] = __float2half(W2[i]);
}

// ---------------- fused: O-combine + residual + LN2 -> g_attn, g_uh ----------------
__global__ void k_oln(const float* __restrict__ w, const float* __restrict__ b) {
    int row = blockIdx.x;
    int t = threadIdx.x;
    int n = row >> 12, q = row & 4095;
    int h = t >> 6, d = t & 63;
    int nh = n * 4 + h;
    float val = 0.f;
#pragma unroll
    for (int ks = 0; ks < KSPLIT; ks++)
        val += g_po[((size_t)(ks * NH + nh) * Ss + q) * Dh + d];
    size_t idx = (size_t)row * Cc + t;
    g_attn[idx] = val;
    float v = val + g_r[idx];

    float s1 = v, s2 = v * v;
#pragma unroll
    for (int o = 16; o; o >>= 1) {
        s1 += __shfl_xor_sync(0xffffffffu, s1, o);
        s2 += __shfl_xor_sync(0xffffffffu, s2, o);
    }
    __shared__ float sm1[8], sm2[8];
    __shared__ float mb, rb;
    int w8 = t >> 5, lane = t & 31;
    if (!lane) { sm1[w8] = s1; sm2[w8] = s2; }
    __syncthreads();
    if (t == 0) {
        float a = 0.f, qq = 0.f;
#pragma unroll
        for (int i = 0; i < 8; i++) { a += sm1[i]; qq += sm2[i]; }
        float mean = a * (1.0f / Cc);
        mb = mean;
        rb = rsqrtf(qq * (1.0f / Cc) - mean * mean + EPSV);
    }
    __syncthreads();
    g_uh[idx] = __float2half((v - mb) * rb * w[t] + b[t]);
}

// ---------------- QKV projection, fp16 mma (Q pre-scaled) ----------------
__global__ __launch_bounds__(256) void k_qkv(const float* __restrict__ WQ,
                                             const float* __restrict__ WK,
                                             const float* __restrict__ WV) {
    int which = blockIdx.y >> 2;
    int h = blockIdx.y & 3;
    int n = blockIdx.z;
    int m0 = blockIdx.x * 128;
    const float* W = (which == 0 ? WQ : which == 1 ? WK : WV) + h * Cc * Dh;
    __half* Out = (which == 0 ? g_Qh : which == 1 ? g_Kh : g_Vh) + (size_t)(n * 4 + h) * Ss * Dh;
    const __half* A = g_normh + (size_t)n * Ss * Cc;
    float oscale = (which == 0) ? SCALE : 1.0f;

    __shared__ __half As[128][88];
    __shared__ __half Bs[64][88];
    int tid = threadIdx.x, lane = tid & 31, wid = tid >> 5;
    int wm = (wid >> 1) * 32;
    int wn = (wid & 1) * 32;
    float acc[2][4][4] = {};

    for (int kb = 0; kb < Cc; kb += 64) {
#pragma unroll
        for (int i = 0; i < 4; i++) {
            int idx = tid + i * 256;
            int r = idx >> 3, c8 = idx & 7;
            *(float4*)&As[r][c8 * 8] = *(const float4*)(A + (size_t)(m0 + r) * Cc + kb + c8 * 8);
        }
#pragma unroll
        for (int i = 0; i < 4; i++) {
            int idx = tid + i * 256;
            int r = idx >> 4, c4 = idx & 15;
            float4 v = *(const float4*)(W + (size_t)(kb + r) * Dh + c4 * 4);
            __half2* d = (__half2*)&Bs[r][c4 * 4];
            d[0] = __floats2half2_rn(v.x, v.y);
            d[1] = __floats2half2_rn(v.z, v.w);
        }
        __syncthreads();
#pragma unroll
        for (int kk = 0; kk < 64; kk += 16) {
            unsigned a[2][4], b[4][2];
#pragma unroll
            for (int mi = 0; mi < 2; mi++)
                ldmx4(a[mi], smem_u32(&As[wm + mi * 16 + (lane & 15)][kk + (lane >> 4) * 8]));
#pragma unroll
            for (int p = 0; p < 2; p++) {
                unsigned r4[4];
                ldmx4t(r4, smem_u32(&Bs[kk + (lane & 7) + ((lane >> 3) & 1) * 8]
                                       [wn + p * 16 + (lane >> 4) * 8]));
                b[2 * p][0] = r4[0]; b[2 * p][1] = r4[1];
                b[2 * p + 1][0] = r4[2]; b[2 * p + 1][1] = r4[3];
            }
#pragma unroll
            for (int mi = 0; mi < 2; mi++)
#pragma unroll
                for (int nj = 0; nj < 4; nj++)
                    mma16816(acc[mi][nj], a[mi], b[nj]);
        }
        __syncthreads();
    }
#pragma unroll
    for (int mi = 0; mi < 2; mi++) {
        int r = m0 + wm + mi * 16 + (lane >> 2);
#pragma unroll
        for (int nj = 0; nj < 4; nj++) {
            int c = wn + nj * 8 + 2 * (lane & 3);
            *(__half2*)(Out + (size_t)r * Dh + c) =
                __floats2half2_rn(acc[mi][nj][0] * oscale, acc[mi][nj][1] * oscale);
            *(__half2*)(Out + (size_t)(r + 8) * Dh + c) =
                __floats2half2_rn(acc[mi][nj][2] * oscale, acc[mi][nj][3] * oscale);
        }
    }
}

// ---------------- pass 1: per-k partial sumexp (no max; |y|<1 by construction) ----------------
__global__ __launch_bounds__(256) void k_stats() {
    int nh = blockIdx.y;
    int qs = blockIdx.z;
    int k0 = blockIdx.x * 128;
    const __half* Kp = g_Kh + (size_t)nh * Ss * Dh;
    const __half* Qp = g_Qh + (size_t)nh * Ss * Dh;
    constexpr int NITER = Ss / 128 / QSPLIT;
    int qbase = qs * (Ss / QSPLIT);

    __shared__ __half As[128][72];
    __shared__ __half Bs[2][128][72];
    __shared__ float sred[2][128];

    int tid = threadIdx.x, lane = tid & 31, wid = tid >> 5;
    int wm = (wid >> 1) * 32;
    int wn = (wid & 1) * 64;

#pragma unroll
    for (int i = 0; i < 4; i++) {
        int idx = tid + i * 256;
        int r = idx >> 3, c8 = idx & 7;
        *(float4*)&As[r][c8 * 8] = *(const float4*)(Kp + (size_t)(k0 + r) * Dh + c8 * 8);
    }
#pragma unroll
    for (int i = 0; i < 4; i++) {
        int idx = tid + i * 256;
        int r = idx >> 3, c8 = idx & 7;
        cpa16(smem_u32(&Bs[0][r][c8 * 8]), Qp + (size_t)(qbase + r) * Dh + c8 * 8);
    }
    cpa_commit();
    __syncthreads();

    unsigned a[2][4][4];
#pragma unroll
    for (int mi = 0; mi < 2; mi++)
#pragma unroll
        for (int t = 0; t < 4; t++)
            ldmx4(a[mi][t], smem_u32(&As[wm + mi * 16 + (lane & 15)][t * 16 + (lane >> 4) * 8]));

    float s_run[4] = {0.f, 0.f, 0.f, 0.f};

    for (int c = 0; c < NITER; c++) {
        __syncthreads();
        if (c + 1 < NITER) {
            int q1 = qbase + (c + 1) * 128;
            int bufn = (c + 1) & 1;
#pragma unroll
            for (int i = 0; i < 4; i++) {
                int idx = tid + i * 256;
                int r = idx >> 3, c8 = idx & 7;
                cpa16(smem_u32(&Bs[bufn][r][c8 * 8]), Qp + (size_t)(q1 + r) * Dh + c8 * 8);
            }
            cpa_commit();
            cpa_wait<1>();
        } else {
            cpa_wait<0>();
        }
        __syncthreads();
        int buf = c & 1;

        float acc[2][8][4] = {};
#pragma unroll
        for (int t = 0; t < 4; t++) {
            unsigned b[8][2];
#pragma unroll
            for (int p = 0; p < 4; p++) {
                unsigned r4[4];
                ldmx4(r4, smem_u32(&Bs[buf][wn + p * 16 + (lane & 7) + (lane >> 4) * 8]
                                         [t * 16 + ((lane >> 3) & 1) * 8]));
                b[2 * p][0] = r4[0]; b[2 * p][1] = r4[1];
                b[2 * p + 1][0] = r4[2]; b[2 * p + 1][1] = r4[3];
            }
#pragma unroll
            for (int mi = 0; mi < 2; mi++)
#pragma unroll
                for (int nj = 0; nj < 8; nj++)
                    mma16816(acc[mi][nj], a[mi][t], b[nj]);
        }
        // sumexp update, no max shift (values bounded by construction)
#pragma unroll
        for (int mi = 0; mi < 2; mi++)
#pragma unroll
            for (int half = 0; half < 2; half++) {
                int slot = mi * 2 + half;
                float s = 0.f;
#pragma unroll
                for (int nj = 0; nj < 8; nj++)
                    s += __expf(acc[mi][nj][2 * half]) + __expf(acc[mi][nj][2 * half + 1]);
                s_run[slot] += s;
            }
    }

#pragma unroll
    for (int off = 1; off <= 2; off <<= 1)
#pragma unroll
        for (int slot = 0; slot < 4; slot++)
            s_run[slot] += __shfl_xor_sync(0xffffffffu, s_run[slot], off);
    __syncthreads();
    if ((lane & 3) == 0) {
#pragma unroll
        for (int mi = 0; mi < 2; mi++)
#pragma unroll
            for (int half = 0; half < 2; half++) {
                int slot = mi * 2 + half;
                int row = wm + mi * 16 + half * 8 + (lane >> 2);
                sred[wid & 1][row] = s_run[slot];
            }
    }
    __syncthreads();
    if (tid < 128)
        g_stp[(qs * NH + nh) * Ss + k0 + tid] = sred[0][tid] + sred[1][tid];
}

// ---------------- combine partial sums -> inverse ----------------
__global__ void k_stcomb() {
    int i = blockIdx.x * 256 + threadIdx.x;
    float s = 0.f;
#pragma unroll
    for (int qs = 0; qs < QSPLIT; qs++)
        s += g_stp[qs * NH * Ss + i];
    g_sti[i] = 1.0f / s;
}

// ---------------- pass 2: flash attn, k split, 32-k chunks ----------------
__global__ __launch_bounds__(256, 2) void k_flash() {
    int nh = blockIdx.y;
    int ks = blockIdx.z;
    int q0 = blockIdx.x * 128;
    const __half* Qp = g_Qh + (size_t)nh * Ss * Dh;
    const __half* Kp = g_Kh + (size_t)nh * Ss * Dh;
    const __half* Vp = g_Vh + (size_t)nh * Ss * Dh;
    const float* Si = g_sti + nh * Ss;
    constexpr int NITER = Ss / 32 / KSPLIT;
    int kbase = ks * (Ss / KSPLIT);

    __shared__ __half Qs[128][72];
    __shared__ __half Ks[2][32][72];
    __shared__ __half Vs[2][32][72];

    int tid = threadIdx.x, lane = tid & 31, wid = tid >> 5;
    int wm = wid * 16;

#pragma unroll
    for (int i = 0; i < 4; i++) {
        int idx = tid + i * 256;
        int r = idx >> 3, c8 = idx & 7;
        *(float4*)&Qs[r][c8 * 8] = *(const float4*)(Qp + (size_t)(q0 + r) * Dh + c8 * 8);
    }
    {
        int r = tid >> 3, c8 = tid & 7;
        cpa16(smem_u32(&Ks[0][r][c8 * 8]), Kp + (size_t)(kbase + r) * Dh + c8 * 8);
        cpa16(smem_u32(&Vs[0][r][c8 * 8]), Vp + (size_t)(kbase + r) * Dh + c8 * 8);
    }
    cpa_commit();
    __syncthreads();

    unsigned aq[4][4];
#pragma unroll
    for (int t = 0; t < 4; t++)
        ldmx4(aq[t], smem_u32(&Qs[wm + (lane & 15)][t * 16 + (lane >> 4) * 8]));

    float accO[8][4] = {};

    for (int c = 0; c < NITER; c++) {
        __syncthreads();
        if (c + 1 < NITER) {
            int kb1 = kbase + (c + 1) * 32;
            int bufn = (c + 1) & 1;
            int r = tid >> 3, c8 = tid & 7;
            cpa16(smem_u32(&Ks[bufn][r][c8 * 8]), Kp + (size_t)(kb1 + r) * Dh + c8 * 8);
            cpa16(smem_u32(&Vs[bufn][r][c8 * 8]), Vp + (size_t)(kb1 + r) * Dh + c8 * 8);
            cpa_commit();
            cpa_wait<1>();
        } else {
            cpa_wait<0>();
        }
        __syncthreads();
        int buf = c & 1;
        int kb = kbase + c * 32;

        float accS[4][4] = {};
#pragma unroll
        for (int t = 0; t < 4; t++) {
            unsigned b[4][2];
#pragma unroll
            for (int p = 0; p < 2; p++) {
                unsigned r4[4];
                ldmx4(r4, smem_u32(&Ks[buf][p * 16 + (lane & 7) + (lane >> 4) * 8]
                                         [t * 16 + ((lane >> 3) & 1) * 8]));
                b[2 * p][0] = r4[0]; b[2 * p][1] = r4[1];
                b[2 * p + 1][0] = r4[2]; b[2 * p + 1][1] = r4[3];
            }
#pragma unroll
            for (int nj = 0; nj < 4; nj++)
                mma16816(accS[nj], aq[t], b[nj]);
        }

        unsigned ap[2][4];
#pragma unroll
        for (int nj = 0; nj < 4; nj++) {
            int col = kb + nj * 8 + 2 * (lane & 3);
            float i0 = Si[col], i1 = Si[col + 1];
            float p0 = __expf(accS[nj][0]) * i0;
            float p1 = __expf(accS[nj][1]) * i1;
            float p2 = __expf(accS[nj][2]) * i0;
            float p3 = __expf(accS[nj][3]) * i1;
            int t = nj >> 1, w2 = (nj & 1) * 2;
            __half2 h0 = __floats2half2_rn(p0, p1);
            __half2 h1 = __floats2half2_rn(p2, p3);
            ap[t][w2]     = *(unsigned*)&h0;
            ap[t][w2 + 1] = *(unsigned*)&h1;
        }

#pragma unroll
        for (int t = 0; t < 2; t++) {
            unsigned bv[8][2];
#pragma unroll
            for (int p = 0; p < 4; p++) {
                unsigned r4[4];
                ldmx4t(r4, smem_u32(&Vs[buf][t * 16 + (lane & 7) + ((lane >> 3) & 1) * 8]
                                          [p * 16 + (lane >> 4) * 8]));
                bv[2 * p][0] = r4[0]; bv[2 * p][1] = r4[1];
                bv[2 * p + 1][0] = r4[2]; bv[2 * p + 1][1] = r4[3];
            }
#pragma unroll
            for (int dj = 0; dj < 8; dj++)
                mma16816(accO[dj], ap[t], bv[dj]);
        }
    }

    float* Po = g_po + ((size_t)(ks * NH + nh) * Ss) * Dh;
#pragma unroll
    for (int dj = 0; dj < 8; dj++) {
        int q = q0 + wm + (lane >> 2);
        int col = dj * 8 + 2 * (lane & 3);
        *(float2*)(Po + (size_t)q * Dh + col) = make_float2(accO[dj][0], accO[dj][1]);
        *(float2*)(Po + (size_t)(q + 8) * Dh + col) = make_float2(accO[dj][2], accO[dj][3]);
    }
}

// ---------------- MLP GEMMs, fp16 mma ----------------
template <int MODE>
__global__ __launch_bounds__(256) void k_mlp(const float* __restrict__ bias) {
    int m0 = blockIdx.x * 128;
    int n0 = blockIdx.y * 64;
    const __half* A = (MODE == 0) ? g_uh : g_h1h;
    const __half* W = (MODE == 0) ? g_W1h : g_W2h;

    __shared__ __half As[128][88];
    __shared__ __half Bs[64][88];
    int tid = threadIdx.x, lane = tid & 31, wid = tid >> 5;
    int wm = (wid >> 1) * 32;
    int wn = (wid & 1) * 32;
    float acc[2][4][4] = {};

    for (int kb = 0; kb < Cc; kb += 64) {
#pragma unroll
        for (int i = 0; i < 4; i++) {
            int idx = tid + i * 256;
            int r = idx >> 3, c8 = idx & 7;
            *(float4*)&As[r][c8 * 8] = *(const float4*)(A + (size_t)(m0 + r) * Cc + kb + c8 * 8);
        }
#pragma unroll
        for (int i = 0; i < 2; i++) {
            int idx = tid + i * 256;
            int r = idx >> 3, c8 = idx & 7;
            *(float4*)&Bs[r][c8 * 8] = *(const float4*)(W + (size_t)(kb + r) * Cc + n0 + c8 * 8);
        }
        __syncthreads();
#pragma unroll
        for (int kk = 0; kk < 64; kk += 16) {
            unsigned a[2][4], b[4][2];
#pragma unroll
            for (int mi = 0; mi < 2; mi++)
                ldmx4(a[mi], smem_u32(&As[wm + mi * 16 + (lane & 15)][kk + (lane >> 4) * 8]));
#pragma unroll
            for (int p = 0; p < 2; p++) {
                unsigned r4[4];
                ldmx4t(r4, smem_u32(&Bs[kk + (lane & 7) + ((lane >> 3) & 1) * 8]
                                       [wn + p * 16 + (lane >> 4) * 8]));
                b[2 * p][0] = r4[0]; b[2 * p][1] = r4[1];
                b[2 * p + 1][0] = r4[2]; b[2 * p + 1][1] = r4[3];
            }
#pragma unroll
            for (int mi = 0; mi < 2; mi++)
#pragma unroll
                for (int nj = 0; nj < 4; nj++)
                    mma16816(acc[mi][nj], a[mi], b[nj]);
        }
        __syncthreads();
    }
#pragma unroll
    for (int mi = 0; mi < 2; mi++) {
#pragma unroll
        for (int half = 0; half < 2; half++) {
            int row = m0 + wm + mi * 16 + half * 8 + (lane >> 2);
#pragma unroll
            for (int nj = 0; nj < 4; nj++) {
                int col = n0 + wn + nj * 8 + 2 * (lane & 3);
                float v0 = acc[mi][nj][2 * half]     + bias[col];
                float v1 = acc[mi][nj][2 * half + 1] + bias[col + 1];
                if (MODE == 0) {
                    v0 = 0.5f * v0 * (1.0f + erff(v0 * 0.70710678118654752f));
                    v1 = 0.5f * v1 * (1.0f + erff(v1 * 0.70710678118654752f));
                    *(__half2*)(g_h1h + (size_t)row * Cc + col) = __floats2half2_rn(v0, v1);
                } else {
                    v0 += g_attn[(size_t)row * Cc + col];
                    v1 += g_attn[(size_t)row * Cc + col + 1];
                    *(float2*)(g_o + (size_t)row * Cc + col) = make_float2(v0, v1);
                }
            }
        }
    }
}

// ---------------- launch ----------------
extern "C" void kernel_launch(void* const* d_in, const int* in_sizes, int n_in,
                              void* d_out, int out_size) {
    const float* x     = (const float*)d_in[0];
    const float* ln1_w = (const float*)d_in[1];
    const float* ln1_b = (const float*)d_in[2];
    const float* WQ    = (const float*)d_in[3];
    const float* WK    = (const float*)d_in[4];
    const float* WV    = (const float*)d_in[5];
    const float* ln2_w = (const float*)d_in[6];
    const float* ln2_b = (const float*)d_in[7];
    const float* W1    = (const float*)d_in[8];
    const float* b1    = (const float*)d_in[9];
    const float* W2    = (const float*)d_in[10];
    const float* b2    = (const float*)d_in[11];
    float* out = (float*)d_out;

    k_tin_ln<<<dim3(Ss / 32, Nb), dim3(32, 8)>>>(x, ln1_w, ln1_b);
    k_cvtw<<<Cc * Cc / 256, 256>>>(W1, W2);

    k_qkv<<<dim3(Ss / 128, 12, Nb), 256>>>(WQ, WK, WV);

    k_stats<<<dim3(Ss / 128, NH, QSPLIT), 256>>>();
    k_stcomb<<<NH * Ss / 256, 256>>>();
    k_flash<<<dim3(Ss / 128, NH, KSPLIT), 256>>>();

    k_oln<<<Nb * Ss, 256>>>(ln2_w, ln2_b);
    k_mlp<0><<<dim3(64, 4), 256>>>(b1);
    k_mlp<1><<<dim3(64, 4), 256>>>(b2);

    k_transpose_out<<<dim3(Ss / 32, Cc / 32, Nb), dim3(32, 8)>>>(out);
}

// round 8
// speedup vs baseline: 6.8570x; 1.0759x over previous
#include <cuda_runtime.h>
#include <cuda_fp16.h>
#include <cstdint>
#include <stdint.h>
#include <math.h>

// ---------------- problem constants ----------------
constexpr int Nb = 2;
constexpr int Cc = 256;
constexpr int Ss = 4096;
constexpr int Hh = 4;
constexpr int Dh = 64;
constexpr int NH = Nb * Hh;
constexpr float EPSV = 1e-5f;
constexpr float QSCALE = (1.0f / 64.0f) * 1.4426950408889634f;  // fold log2(e): exp(y)=exp2(S)
constexpr int QSPLIT = 4;
constexpr int KSPLIT = 4;

// ---------------- device scratch ----------------
__device__ float  g_r    [Nb * Ss * Cc];
__device__ __half g_normh[Nb * Ss * Cc];
__device__ __half g_Qh   [NH * Ss * Dh];   // pre-scaled by QSCALE
__device__ __half g_Kh   [NH * Ss * Dh];
__device__ __half g_Vh   [NH * Ss * Dh];   // post-stats: scaled by inv_k
__device__ float  g_stp  [QSPLIT * NH * Ss];  // partial sumexp
__device__ float  g_po   [KSPLIT * NH * Ss * Dh];
__device__ float  g_attn [Nb * Ss * Cc];
__device__ __half g_uh   [Nb * Ss * Cc];
__device__ __half g_h1h  [Nb * Ss * Cc];
__device__ __half g_W1h  [Cc * Cc];
__device__ __half g_W2h  [Cc * Cc];
__device__ float  g_o    [Nb * Ss * Cc];

// ---------------- helpers ----------------
__device__ __forceinline__ unsigned smem_u32(const void* p) {
    return (unsigned)__cvta_generic_to_shared(p);
}
__device__ __forceinline__ void ldmx4(unsigned* r, unsigned a) {
    asm volatile("ldmatrix.sync.aligned.m8n8.x4.shared.b16 {%0,%1,%2,%3},[%4];"
                 : "=r"(r[0]), "=r"(r[1]), "=r"(r[2]), "=r"(r[3]) : "r"(a));
}
__device__ __forceinline__ void ldmx4t(unsigned* r, unsigned a) {
    asm volatile("ldmatrix.sync.aligned.m8n8.x4.trans.shared.b16 {%0,%1,%2,%3},[%4];"
                 : "=r"(r[0]), "=r"(r[1]), "=r"(r[2]), "=r"(r[3]) : "r"(a));
}
__device__ __forceinline__ void mma16816(float* c, const unsigned* a, const unsigned* b) {
    asm volatile(
        "mma.sync.aligned.m16n8k16.row.col.f32.f16.f16.f32 "
        "{%0,%1,%2,%3},{%4,%5,%6,%7},{%8,%9},{%0,%1,%2,%3};"
        : "+f"(c[0]), "+f"(c[1]), "+f"(c[2]), "+f"(c[3])
        : "r"(a[0]), "r"(a[1]), "r"(a[2]), "r"(a[3]), "r"(b[0]), "r"(b[1]));
}
__device__ __forceinline__ void cpa16(unsigned dst, const void* src) {
    asm volatile("cp.async.ca.shared.global [%0], [%1], 16;" :: "r"(dst), "l"(src));
}
__device__ __forceinline__ void cpa_commit() {
    asm volatile("cp.async.commit_group;");
}
template <int N>
__device__ __forceinline__ void cpa_wait() {
    asm volatile("cp.async.wait_group %0;" :: "n"(N));
}

// ---------------- fused: transpose x[n,c,s] -> r[n,s,c] + LN1 -> normh ----------------
__global__ void k_tin_ln(const float* __restrict__ x,
                         const float* __restrict__ w, const float* __restrict__ b) {
    __shared__ float t[256][33];
    int n = blockIdx.y, s0 = blockIdx.x * 32;
    int tx = threadIdx.x, ty = threadIdx.y;
#pragma unroll
    for (int i = 0; i < 32; i++)
        t[ty + 8 * i][tx] = x[((size_t)(n * Cc + ty + 8 * i)) * Ss + s0 + tx];
    __syncthreads();
    int lane = tx;
#pragma unroll
    for (int j = 0; j < 4; j++) {
        int s = ty * 4 + j;
        float vals[8];
        float s1 = 0.f, s2 = 0.f;
#pragma unroll
        for (int u = 0; u < 8; u++) {
            float v = t[lane + 32 * u][s];
            vals[u] = v; s1 += v; s2 += v * v;
        }
#pragma unroll
        for (int o = 16; o; o >>= 1) {
            s1 += __shfl_xor_sync(0xffffffffu, s1, o);
            s2 += __shfl_xor_sync(0xffffffffu, s2, o);
        }
        float mean = s1 * (1.0f / Cc);
        float rstd = rsqrtf(s2 * (1.0f / Cc) - mean * mean + EPSV);
        size_t rowo = ((size_t)n * Ss + s0 + s) * Cc;
#pragma unroll
        for (int u = 0; u < 8; u++) {
            int c = lane + 32 * u;
            g_r[rowo + c] = vals[u];
            g_normh[rowo + c] = __float2half((vals[u] - mean) * rstd * w[c] + b[c]);
        }
    }
}

// ---------------- transpose out ----------------
__global__ void k_transpose_out(float* __restrict__ out) {
    __shared__ float t[32][33];
    int n = blockIdx.z;
    int s0 = blockIdx.x * 32, c0 = blockIdx.y * 32;
    int tx = threadIdx.x, ty = threadIdx.y;
#pragma unroll
    for (int i = 0; i < 4; i++)
        t[ty + 8 * i][tx] = g_o[((size_t)(n * Ss + s0 + ty + 8 * i)) * Cc + c0 + tx];
    __syncthreads();
#pragma unroll
    for (int i = 0; i < 4; i++)
        out[((size_t)(n * Cc + c0 + ty + 8 * i)) * Ss + s0 + tx] = t[tx][ty + 8 * i];
}

// ---------------- weight fp32 -> fp16 ----------------
__global__ void k_cvtw(const float* __restrict__ W1, const float* __restrict__ W2) {
    int i = blockIdx.x * 256 + threadIdx.x;
    g_W1h[i] = __float2half(W1[i]);
    g_W2h[i] = __float2half(W2[i]);
}

// ---------------- fused: O-combine + residual + LN2 -> g_attn, g_uh ----------------
__global__ void k_oln(const float* __restrict__ w, const float* __restrict__ b) {
    int row = blockIdx.x;
    int t = threadIdx.x;
    int n = row >> 12, q = row & 4095;
    int h = t >> 6, d = t & 63;
    int nh = n * 4 + h;
    float val = 0.f;
#pragma unroll
    for (int ks = 0; ks < KSPLIT; ks++)
        val += g_po[((size_t)(ks * NH + nh) * Ss + q) * Dh + d];
    size_t idx = (size_t)row * Cc + t;
    g_attn[idx] = val;
    float v = val + g_r[idx];

    float s1 = v, s2 = v * v;
#pragma unroll
    for (int o = 16; o; o >>= 1) {
        s1 += __shfl_xor_sync(0xffffffffu, s1, o);
        s2 += __shfl_xor_sync(0xffffffffu, s2, o);
    }
    __shared__ float sm1[8], sm2[8];
    __shared__ float mb, rb;
    int w8 = t >> 5, lane = t & 31;
    if (!lane) { sm1[w8] = s1; sm2[w8] = s2; }
    __syncthreads();
    if (t == 0) {
        float a = 0.f, qq = 0.f;
#pragma unroll
        for (int i = 0; i < 8; i++) { a += sm1[i]; qq += sm2[i]; }
        float mean = a * (1.0f / Cc);
        mb = mean;
        rb = rsqrtf(qq * (1.0f / Cc) - mean * mean + EPSV);
    }
    __syncthreads();
    g_uh[idx] = __float2half((v - mb) * rb * w[t] + b[t]);
}

// ---------------- QKV projection, fp16 mma (Q pre-scaled by QSCALE) ----------------
__global__ __launch_bounds__(256) void k_qkv(const float* __restrict__ WQ,
                                             const float* __restrict__ WK,
                                             const float* __restrict__ WV) {
    int which = blockIdx.y >> 2;
    int h = blockIdx.y & 3;
    int n = blockIdx.z;
    int m0 = blockIdx.x * 128;
    const float* W = (which == 0 ? WQ : which == 1 ? WK : WV) + h * Cc * Dh;
    __half* Out = (which == 0 ? g_Qh : which == 1 ? g_Kh : g_Vh) + (size_t)(n * 4 + h) * Ss * Dh;
    const __half* A = g_normh + (size_t)n * Ss * Cc;
    float oscale = (which == 0) ? QSCALE : 1.0f;

    __shared__ __half As[128][88];
    __shared__ __half Bs[64][88];
    int tid = threadIdx.x, lane = tid & 31, wid = tid >> 5;
    int wm = (wid >> 1) * 32;
    int wn = (wid & 1) * 32;
    float acc[2][4][4] = {};

    for (int kb = 0; kb < Cc; kb += 64) {
#pragma unroll
        for (int i = 0; i < 4; i++) {
            int idx = tid + i * 256;
            int r = idx >> 3, c8 = idx & 7;
            *(float4*)&As[r][c8 * 8] = *(const float4*)(A + (size_t)(m0 + r) * Cc + kb + c8 * 8);
        }
#pragma unroll
        for (int i = 0; i < 4; i++) {
            int idx = tid + i * 256;
            int r = idx >> 4, c4 = idx & 15;
            float4 v = *(const float4*)(W + (size_t)(kb + r) * Dh + c4 * 4);
            __half2* d = (__half2*)&Bs[r][c4 * 4];
            d[0] = __floats2half2_rn(v.x, v.y);
            d[1] = __floats2half2_rn(v.z, v.w);
        }
        __syncthreads();
#pragma unroll
        for (int kk = 0; kk < 64; kk += 16) {
            unsigned a[2][4], b[4][2];
#pragma unroll
            for (int mi = 0; mi < 2; mi++)
                ldmx4(a[mi], smem_u32(&As[wm + mi * 16 + (lane & 15)][kk + (lane >> 4) * 8]));
#pragma unroll
            for (int p = 0; p < 2; p++) {
                unsigned r4[4];
                ldmx4t(r4, smem_u32(&Bs[kk + (lane & 7) + ((lane >> 3) & 1) * 8]
                                       [wn + p * 16 + (lane >> 4) * 8]));
                b[2 * p][0] = r4[0]; b[2 * p][1] = r4[1];
                b[2 * p + 1][0] = r4[2]; b[2 * p + 1][1] = r4[3];
            }
#pragma unroll
            for (int mi = 0; mi < 2; mi++)
#pragma unroll
                for (int nj = 0; nj < 4; nj++)
                    mma16816(acc[mi][nj], a[mi], b[nj]);
        }
        __syncthreads();
    }
#pragma unroll
    for (int mi = 0; mi < 2; mi++) {
        int r = m0 + wm + mi * 16 + (lane >> 2);
#pragma unroll
        for (int nj = 0; nj < 4; nj++) {
            int c = wn + nj * 8 + 2 * (lane & 3);
            *(__half2*)(Out + (size_t)r * Dh + c) =
                __floats2half2_rn(acc[mi][nj][0] * oscale, acc[mi][nj][1] * oscale);
            *(__half2*)(Out + (size_t)(r + 8) * Dh + c) =
                __floats2half2_rn(acc[mi][nj][2] * oscale, acc[mi][nj][3] * oscale);
        }
    }
}

// ---------------- pass 1: per-k partial sum of exp2(S), fp16x2 exp ----------------
__global__ __launch_bounds__(256) void k_stats() {
    int nh = blockIdx.y;
    int qs = blockIdx.z;
    int k0 = blockIdx.x * 128;
    const __half* Kp = g_Kh + (size_t)nh * Ss * Dh;
    const __half* Qp = g_Qh + (size_t)nh * Ss * Dh;
    constexpr int NITER = Ss / 128 / QSPLIT;
    int qbase = qs * (Ss / QSPLIT);

    __shared__ __half As[128][72];
    __shared__ __half Bs[2][128][72];
    __shared__ float sred[2][128];

    int tid = threadIdx.x, lane = tid & 31, wid = tid >> 5;
    int wm = (wid >> 1) * 32;
    int wn = (wid & 1) * 64;

#pragma unroll
    for (int i = 0; i < 4; i++) {
        int idx = tid + i * 256;
        int r = idx >> 3, c8 = idx & 7;
        *(float4*)&As[r][c8 * 8] = *(const float4*)(Kp + (size_t)(k0 + r) * Dh + c8 * 8);
    }
#pragma unroll
    for (int i = 0; i < 4; i++) {
        int idx = tid + i * 256;
        int r = idx >> 3, c8 = idx & 7;
        cpa16(smem_u32(&Bs[0][r][c8 * 8]), Qp + (size_t)(qbase + r) * Dh + c8 * 8);
    }
    cpa_commit();
    __syncthreads();

    unsigned a[2][4][4];
#pragma unroll
    for (int mi = 0; mi < 2; mi++)
#pragma unroll
        for (int t = 0; t < 4; t++)
            ldmx4(a[mi][t], smem_u32(&As[wm + mi * 16 + (lane & 15)][t * 16 + (lane >> 4) * 8]));

    float s_run[4] = {0.f, 0.f, 0.f, 0.f};

    for (int c = 0; c < NITER; c++) {
        __syncthreads();
        if (c + 1 < NITER) {
            int q1 = qbase + (c + 1) * 128;
            int bufn = (c + 1) & 1;
#pragma unroll
            for (int i = 0; i < 4; i++) {
                int idx = tid + i * 256;
                int r = idx >> 3, c8 = idx & 7;
                cpa16(smem_u32(&Bs[bufn][r][c8 * 8]), Qp + (size_t)(q1 + r) * Dh + c8 * 8);
            }
            cpa_commit();
            cpa_wait<1>();
        } else {
            cpa_wait<0>();
        }
        __syncthreads();
        int buf = c & 1;

        float acc[2][8][4] = {};
#pragma unroll
        for (int t = 0; t < 4; t++) {
            unsigned b[8][2];
#pragma unroll
            for (int p = 0; p < 4; p++) {
                unsigned r4[4];
                ldmx4(r4, smem_u32(&Bs[buf][wn + p * 16 + (lane & 7) + (lane >> 4) * 8]
                                         [t * 16 + ((lane >> 3) & 1) * 8]));
                b[2 * p][0] = r4[0]; b[2 * p][1] = r4[1];
                b[2 * p + 1][0] = r4[2]; b[2 * p + 1][1] = r4[3];
            }
#pragma unroll
            for (int mi = 0; mi < 2; mi++)
#pragma unroll
                for (int nj = 0; nj < 8; nj++)
                    mma16816(acc[mi][nj], a[mi][t], b[nj]);
        }
        // sum exp2(S) via f16x2 MUFU, half2 accumulate, fp32 flush per iter
#pragma unroll
        for (int mi = 0; mi < 2; mi++) {
            __half2 h0 = __float2half2_rn(0.f), h1 = __float2half2_rn(0.f);
#pragma unroll
            for (int nj = 0; nj < 8; nj++) {
                __half2 e0 = h2exp2(__floats2half2_rn(acc[mi][nj][0], acc[mi][nj][1]));
                __half2 e1 = h2exp2(__floats2half2_rn(acc[mi][nj][2], acc[mi][nj][3]));
                h0 = __hadd2(h0, e0);
                h1 = __hadd2(h1, e1);
            }
            float2 f0 = __half22float2(h0), f1 = __half22float2(h1);
            s_run[mi * 2 + 0] += f0.x + f0.y;
            s_run[mi * 2 + 1] += f1.x + f1.y;
        }
    }

#pragma unroll
    for (int off = 1; off <= 2; off <<= 1)
#pragma unroll
        for (int slot = 0; slot < 4; slot++)
            s_run[slot] += __shfl_xor_sync(0xffffffffu, s_run[slot], off);
    __syncthreads();
    if ((lane & 3) == 0) {
#pragma unroll
        for (int mi = 0; mi < 2; mi++)
#pragma unroll
            for (int half = 0; half < 2; half++) {
                int slot = mi * 2 + half;
                int row = wm + mi * 16 + half * 8 + (lane >> 2);
                sred[wid & 1][row] = s_run[slot];
            }
    }
    __syncthreads();
    if (tid < 128)
        g_stp[(qs * NH + nh) * Ss + k0 + tid] = sred[0][tid] + sred[1][tid];
}

// ---------------- combine partial sums + scale V by inv_k (in place) ----------------
// grid NH*Ss/64 = 512 blocks, 256 threads
__global__ void k_stvs() {
    int base = blockIdx.x * 64;        // global k-row index into [0, NH*Ss)
    __shared__ float sinv[64];
    int tid = threadIdx.x;
    if (tid < 64) {
        int i = base + tid;
        float s = 0.f;
#pragma unroll
        for (int qs = 0; qs < QSPLIT; qs++)
            s += g_stp[qs * NH * Ss + i];
        sinv[tid] = 1.0f / s;
    }
    __syncthreads();
    __half2* V2 = (__half2*)g_Vh;
#pragma unroll
    for (int j = 0; j < 8; j++) {
        int idx = tid + j * 256;        // 0..2047 = 64 rows x 32 half2
        int row = idx >> 5, c2 = idx & 31;
        float inv = sinv[row];
        size_t o = (size_t)(base + row) * 32 + c2;
        float2 vf = __half22float2(V2[o]);
        V2[o] = __floats2half2_rn(vf.x * inv, vf.y * inv);
    }
}

// ---------------- pass 2: flash attn; P = exp2(S) in f16x2, V pre-normalized ----------------
__global__ __launch_bounds__(256, 2) void k_flash() {
    int nh = blockIdx.y;
    int ks = blockIdx.z;
    int q0 = blockIdx.x * 128;
    const __half* Qp = g_Qh + (size_t)nh * Ss * Dh;
    const __half* Kp = g_Kh + (size_t)nh * Ss * Dh;
    const __half* Vp = g_Vh + (size_t)nh * Ss * Dh;
    constexpr int NITER = Ss / 32 / KSPLIT;
    int kbase = ks * (Ss / KSPLIT);

    __shared__ __half Qs[128][72];
    __shared__ __half Ks[2][32][72];
    __shared__ __half Vs[2][32][72];

    int tid = threadIdx.x, lane = tid & 31, wid = tid >> 5;
    int wm = wid * 16;

#pragma unroll
    for (int i = 0; i < 4; i++) {
        int idx = tid + i * 256;
        int r = idx >> 3, c8 = idx & 7;
        *(float4*)&Qs[r][c8 * 8] = *(const float4*)(Qp + (size_t)(q0 + r) * Dh + c8 * 8);
    }
    {
        int r = tid >> 3, c8 = tid & 7;
        cpa16(smem_u32(&Ks[0][r][c8 * 8]), Kp + (size_t)(kbase + r) * Dh + c8 * 8);
        cpa16(smem_u32(&Vs[0][r][c8 * 8]), Vp + (size_t)(kbase + r) * Dh + c8 * 8);
    }
    cpa_commit();
    __syncthreads();

    unsigned aq[4][4];
#pragma unroll
    for (int t = 0; t < 4; t++)
        ldmx4(aq[t], smem_u32(&Qs[wm + (lane & 15)][t * 16 + (lane >> 4) * 8]));

    float accO[8][4] = {};

    for (int c = 0; c < NITER; c++) {
        __syncthreads();
        if (c + 1 < NITER) {
            int kb1 = kbase + (c + 1) * 32;
            int bufn = (c + 1) & 1;
            int r = tid >> 3, c8 = tid & 7;
            cpa16(smem_u32(&Ks[bufn][r][c8 * 8]), Kp + (size_t)(kb1 + r) * Dh + c8 * 8);
            cpa16(smem_u32(&Vs[bufn][r][c8 * 8]), Vp + (size_t)(kb1 + r) * Dh + c8 * 8);
            cpa_commit();
            cpa_wait<1>();
        } else {
            cpa_wait<0>();
        }
        __syncthreads();
        int buf = c & 1;

        float accS[4][4] = {};
#pragma unroll
        for (int t = 0; t < 4; t++) {
            unsigned b[4][2];
#pragma unroll
            for (int p = 0; p < 2; p++) {
                unsigned r4[4];
                ldmx4(r4, smem_u32(&Ks[buf][p * 16 + (lane & 7) + (lane >> 4) * 8]
                                         [t * 16 + ((lane >> 3) & 1) * 8]));
                b[2 * p][0] = r4[0]; b[2 * p][1] = r4[1];
                b[2 * p + 1][0] = r4[2]; b[2 * p + 1][1] = r4[3];
            }
#pragma unroll
            for (int nj = 0; nj < 4; nj++)
                mma16816(accS[nj], aq[t], b[nj]);
        }

        // P = exp2(S) directly in f16x2; V already carries inv_k
        unsigned ap[2][4];
#pragma unroll
        for (int nj = 0; nj < 4; nj++) {
            __half2 e0 = h2exp2(__floats2half2_rn(accS[nj][0], accS[nj][1]));
            __half2 e1 = h2exp2(__floats2half2_rn(accS[nj][2], accS[nj][3]));
            int t = nj >> 1, w2 = (nj & 1) * 2;
            ap[t][w2]     = *(unsigned*)&e0;
            ap[t][w2 + 1] = *(unsigned*)&e1;
        }

#pragma unroll
        for (int t = 0; t < 2; t++) {
            unsigned bv[8][2];
#pragma unroll
            for (int p = 0; p < 4; p++) {
                unsigned r4[4];
                ldmx4t(r4, smem_u32(&Vs[buf][t * 16 + (lane & 7) + ((lane >> 3) & 1) * 8]
                                          [p * 16 + (lane >> 4) * 8]));
                bv[2 * p][0] = r4[0]; bv[2 * p][1] = r4[1];
                bv[2 * p + 1][0] = r4[2]; bv[2 * p + 1][1] = r4[3];
            }
#pragma unroll
            for (int dj = 0; dj < 8; dj++)
                mma16816(accO[dj], ap[t], bv[dj]);
        }
    }

    float* Po = g_po + ((size_t)(ks * NH + nh) * Ss) * Dh;
#pragma unroll
    for (int dj = 0; dj < 8; dj++) {
        int q = q0 + wm + (lane >> 2);
        int col = dj * 8 + 2 * (lane & 3);
        *(float2*)(Po + (size_t)q * Dh + col) = make_float2(accO[dj][0], accO[dj][1]);
        *(float2*)(Po + (size_t)(q + 8) * Dh + col) = make_float2(accO[dj][2], accO[dj][3]);
    }
}

// ---------------- MLP GEMMs, fp16 mma, 64x64 blocks ----------------
// MODE 0: g_h1h = half(gelu(uh @ W1h + b1));  MODE 1: g_o = h1h @ W2h + b2 + g_attn
// grid (128, 4), block 256 = 8 warps (4m x 2n); warp tile 16m x 32n
template <int MODE>
__global__ __launch_bounds__(256) void k_mlp(const float* __restrict__ bias) {
    int m0 = blockIdx.x * 64;
    int n0 = blockIdx.y * 64;
    const __half* A = (MODE == 0) ? g_uh : g_h1h;
    const __half* W = (MODE == 0) ? g_W1h : g_W2h;

    __shared__ __half As[64][88];
    __shared__ __half Bs[64][88];
    int tid = threadIdx.x, lane = tid & 31, wid = tid >> 5;
    int wm = (wid >> 1) * 16;
    int wn = (wid & 1) * 32;
    float acc[4][4] = {};

    for (int kb = 0; kb < Cc; kb += 64) {
#pragma unroll
        for (int i = 0; i < 2; i++) {
            int idx = tid + i * 256;
            int r = idx >> 3, c8 = idx & 7;
            *(float4*)&As[r][c8 * 8] = *(const float4*)(A + (size_t)(m0 + r) * Cc + kb + c8 * 8);
            *(float4*)&Bs[r][c8 * 8] = *(const float4*)(W + (size_t)(kb + r) * Cc + n0 + c8 * 8);
        }
        __syncthreads();
#pragma unroll
        for (int kk = 0; kk < 64; kk += 16) {
            unsigned a[4], b[4][2];
            ldmx4(a, smem_u32(&As[wm + (lane & 15)][kk + (lane >> 4) * 8]));
#pragma unroll
            for (int p = 0; p < 2; p++) {
                unsigned r4[4];
                ldmx4t(r4, smem_u32(&Bs[kk + (lane & 7) + ((lane >> 3) & 1) * 8]
                                       [wn + p * 16 + (lane >> 4) * 8]));
                b[2 * p][0] = r4[0]; b[2 * p][1] = r4[1];
                b[2 * p + 1][0] = r4[2]; b[2 * p + 1][1] = r4[3];
            }
#pragma unroll
            for (int nj = 0; nj < 4; nj++)
                mma16816(acc[nj], a, b[nj]);
        }
        __syncthreads();
    }
#pragma unroll
    for (int half = 0; half < 2; half++) {
        int row = m0 + wm + half * 8 + (lane >> 2);
#pragma unroll
        for (int nj = 0; nj < 4; nj++) {
            int col = n0 + wn + nj * 8 + 2 * (lane & 3);
            float v0 = acc[nj][2 * half]     + bias[col];
            float v1 = acc[nj][2 * half + 1] + bias[col + 1];
            if (MODE == 0) {
                v0 = 0.5f * v0 * (1.0f + erff(v0 * 0.70710678118654752f));
                v1 = 0.5f * v1 * (1.0f + erff(v1 * 0.70710678118654752f));
                *(__half2*)(g_h1h + (size_t)row * Cc + col) = __floats2half2_rn(v0, v1);
            } else {
                v0 += g_attn[(size_t)row * Cc + col];
                v1 += g_attn[(size_t)row * Cc + col + 1];
                *(float2*)(g_o + (size_t)row * Cc + col) = make_float2(v0, v1);
            }
        }
    }
}

// ---------------- launch ----------------
extern "C" void kernel_launch(void* const* d_in, const int* in_sizes, int n_in,
                              void* d_out, int out_size) {
    const float* x     = (const float*)d_in[0];
    const float* ln1_w = (const float*)d_in[1];
    const float* ln1_b = (const float*)d_in[2];
    const float* WQ    = (const float*)d_in[3];
    const float* WK    = (const float*)d_in[4];
    const float* WV    = (const float*)d_in[5];
    const float* ln2_w = (const float*)d_in[6];
    const float* ln2_b = (const float*)d_in[7];
    const float* W1    = (const float*)d_in[8];
    const float* b1    = (const float*)d_in[9];
    const float* W2    = (const float*)d_in[10];
    const float* b2    = (const float*)d_in[11];
    float* out = (float*)d_out;

    k_tin_ln<<<dim3(Ss / 32, Nb), dim3(32, 8)>>>(x, ln1_w, ln1_b);
    k_cvtw<<<Cc * Cc / 256, 256>>>(W1, W2);

    k_qkv<<<dim3(Ss / 128, 12, Nb), 256>>>(WQ, WK, WV);

    k_stats<<<dim3(Ss / 128, NH, QSPLIT), 256>>>();
    k_stvs<<<NH * Ss / 64, 256>>>();
    k_flash<<<dim3(Ss / 128, NH, KSPLIT), 256>>>();

    k_oln<<<Nb * Ss, 256>>>(ln2_w, ln2_b);
    k_mlp<0><<<dim3(128, 4), 256>>>(b1);
    k_mlp<1><<<dim3(128, 4), 256>>>(b2);

    k_transpose_out<<<dim3(Ss / 32, Cc / 32, Nb), dim3(32, 8)>>>(out);
}